// round 1
// baseline (speedup 1.0000x reference)
#include <cuda_runtime.h>
#include <math.h>

// Problem constants
#define T_TOK   8192            // B*S tokens
#define D_MODEL 1024
#define F_FF    2048
#define NE      8               // experts
#define TOPK    2
#define CAP     2560            // ceil(1.25 * 16384 / 8)
#define NA      (T_TOK * TOPK)  // 16384 assignments

// Device scratch (no allocations allowed)
__device__ float g_H[(size_t)NE * CAP * F_FF];   // [E, cap, F] fp32 intermediate (~168 MB)
__device__ int   g_topk_i[NA];
__device__ float g_topk_w[NA];
__device__ int   g_slot_tok[NE * CAP];
__device__ float g_slot_w[NE * CAP];
__device__ int   g_cnt[NE];

// ---------------------------------------------------------------------------
// K0: zero output (harness poisons d_out; GEMM2 scatter uses atomicAdd)
// ---------------------------------------------------------------------------
__global__ void zero_kernel(float4* __restrict__ out, int n4) {
    int i = blockIdx.x * blockDim.x + threadIdx.x;
    if (i < n4) out[i] = make_float4(0.f, 0.f, 0.f, 0.f);
}

// ---------------------------------------------------------------------------
// K1: router — logits = x @ router_w + b, softmax, top-2, normalize.
// One warp per token.
// ---------------------------------------------------------------------------
__global__ void router_kernel(const float* __restrict__ x,
                              const float* __restrict__ rw,
                              const float* __restrict__ rb) {
    int warp = (blockIdx.x * blockDim.x + threadIdx.x) >> 5;
    int lane = threadIdx.x & 31;
    if (warp >= T_TOK) return;
    const float* xr = x + (size_t)warp * D_MODEL;

    float acc[NE];
#pragma unroll
    for (int e = 0; e < NE; e++) acc[e] = 0.f;

    for (int d = lane; d < D_MODEL; d += 32) {
        float xv = xr[d];
        const float* w = rw + d * NE;
#pragma unroll
        for (int e = 0; e < NE; e++) acc[e] += xv * w[e];
    }
#pragma unroll
    for (int e = 0; e < NE; e++) {
#pragma unroll
        for (int o = 16; o > 0; o >>= 1)
            acc[e] += __shfl_down_sync(0xffffffffu, acc[e], o);
    }
    if (lane == 0) {
        float l[NE];
#pragma unroll
        for (int e = 0; e < NE; e++) l[e] = acc[e] + rb[e];
        float m = l[0];
#pragma unroll
        for (int e = 1; e < NE; e++) m = fmaxf(m, l[e]);
        float p[NE];
        float s = 0.f;
#pragma unroll
        for (int e = 0; e < NE; e++) { p[e] = expf(l[e] - m); s += p[e]; }
        float inv = 1.f / s;
#pragma unroll
        for (int e = 0; e < NE; e++) p[e] *= inv;
        // top-1 (first occurrence on ties, matching lax.top_k)
        int i1 = 0; float p1 = p[0];
#pragma unroll
        for (int e = 1; e < NE; e++) if (p[e] > p1) { p1 = p[e]; i1 = e; }
        int i2 = -1; float p2 = -1.f;
#pragma unroll
        for (int e = 0; e < NE; e++) if (e != i1 && p[e] > p2) { p2 = p[e]; i2 = e; }
        float sum = fmaxf(p1 + p2, 1e-9f);
        g_topk_i[warp * 2 + 0] = i1;
        g_topk_i[warp * 2 + 1] = i2;
        g_topk_w[warp * 2 + 0] = p1 / sum;
        g_topk_w[warp * 2 + 1] = p2 / sum;
    }
}

// ---------------------------------------------------------------------------
// K2: stable rank within expert (matches argsort-stable semantics), capacity
// drop, slot table build. Single block of 256 threads, 64 assignments each.
// ---------------------------------------------------------------------------
__global__ void rank_kernel() {
    __shared__ int cnts[256][NE];
    int tid = threadIdx.x;
    int base = tid * (NA / 256);   // 64 per thread

    int local[NE];
#pragma unroll
    for (int e = 0; e < NE; e++) local[e] = 0;
    for (int a = base; a < base + NA / 256; a++) local[g_topk_i[a]]++;
#pragma unroll
    for (int e = 0; e < NE; e++) cnts[tid][e] = local[e];
    __syncthreads();

    if (tid < NE) {
        int run = 0;
        for (int i = 0; i < 256; i++) { int t = cnts[i][tid]; cnts[i][tid] = run; run += t; }
        g_cnt[tid] = min(run, CAP);
    }
    __syncthreads();

#pragma unroll
    for (int e = 0; e < NE; e++) local[e] = cnts[tid][e];
    for (int a = base; a < base + NA / 256; a++) {
        int e = g_topk_i[a];
        int r = local[e]++;
        if (r < CAP) {
            int slot = e * CAP + r;
            g_slot_tok[slot] = a >> 1;       // token index
            g_slot_w[slot]   = g_topk_w[a];
        }
    }
}

// ---------------------------------------------------------------------------
// K3: GEMM1 — H[e,c,:] = gelu( gather(x)[c,:] @ w1[e] + b1[e] )
// 128x128x16 tile, 256 threads, 8x8 per thread. A gathered via slot_tok.
// ---------------------------------------------------------------------------
__global__ __launch_bounds__(256)
void gemm1_kernel(const float* __restrict__ x,
                  const float* __restrict__ w1g,
                  const float* __restrict__ b1g) {
    int e = blockIdx.z;
    int cnt = g_cnt[e];
    int row0 = blockIdx.y * 128;
    if (row0 >= cnt) return;               // data-dependent tile skip
    int col0 = blockIdx.x * 128;

    __shared__ float As[16][128];          // transposed: [k][m]
    __shared__ float Bs[16][128];          // [k][n]

    int tid = threadIdx.x;
    int ar0 = tid >> 2;                    // A rows: ar0, ar0+64
    int ak4 = (tid & 3) * 4;               // A k-offset (float4)
    int tok0 = -1, tok1 = -1;
    {
        int r = row0 + ar0;
        if (r < cnt) tok0 = g_slot_tok[e * CAP + r];
        r = row0 + ar0 + 64;
        if (r < cnt) tok1 = g_slot_tok[e * CAP + r];
    }
    int br0 = tid >> 5;                    // B rows: br0, br0+8
    int bc4 = (tid & 31) * 4;
    const float* Bg = w1g + (size_t)e * D_MODEL * F_FF + col0;

    int ty = tid >> 4, tx = tid & 15;
    float acc[8][8];
#pragma unroll
    for (int i = 0; i < 8; i++)
#pragma unroll
        for (int j = 0; j < 8; j++) acc[i][j] = 0.f;

    for (int k0 = 0; k0 < D_MODEL; k0 += 16) {
        float4 a0 = make_float4(0.f, 0.f, 0.f, 0.f);
        float4 a1 = make_float4(0.f, 0.f, 0.f, 0.f);
        if (tok0 >= 0) a0 = *(const float4*)(x + (size_t)tok0 * D_MODEL + k0 + ak4);
        if (tok1 >= 0) a1 = *(const float4*)(x + (size_t)tok1 * D_MODEL + k0 + ak4);
        float4 bv0 = *(const float4*)(Bg + (size_t)(k0 + br0) * F_FF + bc4);
        float4 bv1 = *(const float4*)(Bg + (size_t)(k0 + br0 + 8) * F_FF + bc4);
        __syncthreads();
        As[ak4 + 0][ar0] = a0.x; As[ak4 + 1][ar0] = a0.y;
        As[ak4 + 2][ar0] = a0.z; As[ak4 + 3][ar0] = a0.w;
        As[ak4 + 0][ar0 + 64] = a1.x; As[ak4 + 1][ar0 + 64] = a1.y;
        As[ak4 + 2][ar0 + 64] = a1.z; As[ak4 + 3][ar0 + 64] = a1.w;
        *(float4*)&Bs[br0][bc4]     = bv0;
        *(float4*)&Bs[br0 + 8][bc4] = bv1;
        __syncthreads();
#pragma unroll
        for (int kk = 0; kk < 16; kk++) {
            float af[8], bf[8];
            *(float4*)(af)     = *(const float4*)&As[kk][ty * 8];
            *(float4*)(af + 4) = *(const float4*)&As[kk][ty * 8 + 4];
            *(float4*)(bf)     = *(const float4*)&Bs[kk][tx * 8];
            *(float4*)(bf + 4) = *(const float4*)&Bs[kk][tx * 8 + 4];
#pragma unroll
            for (int i = 0; i < 8; i++)
#pragma unroll
                for (int j = 0; j < 8; j++) acc[i][j] += af[i] * bf[j];
        }
    }
    // epilogue: bias + exact gelu -> H
    const float* bp = b1g + e * F_FF + col0;
    float* Hp = g_H + ((size_t)e * CAP + row0) * F_FF + col0;
#pragma unroll
    for (int i = 0; i < 8; i++) {
        int r = ty * 8 + i;
#pragma unroll
        for (int j = 0; j < 8; j++) {
            float v = acc[i][j] + bp[tx * 8 + j];
            v = 0.5f * v * (1.f + erff(v * 0.70710678118654752f));
            Hp[(size_t)r * F_FF + tx * 8 + j] = v;
        }
    }
}

// ---------------------------------------------------------------------------
// K4: GEMM2 — eo = H[e] @ w2[e] + b2[e], then out[tok] += eo * gate_w
// ---------------------------------------------------------------------------
__global__ __launch_bounds__(256)
void gemm2_kernel(const float* __restrict__ w2g,
                  const float* __restrict__ b2g,
                  float* __restrict__ out) {
    int e = blockIdx.z;
    int cnt = g_cnt[e];
    int row0 = blockIdx.y * 128;
    if (row0 >= cnt) return;
    int col0 = blockIdx.x * 128;

    __shared__ float As[16][128];
    __shared__ float Bs[16][128];

    int tid = threadIdx.x;
    int ar0 = tid >> 2;
    int ak4 = (tid & 3) * 4;
    const float* Ag = g_H + ((size_t)e * CAP + row0) * F_FF;
    int br0 = tid >> 5;
    int bc4 = (tid & 31) * 4;
    const float* Bg = w2g + (size_t)e * F_FF * D_MODEL + col0;

    int ty = tid >> 4, tx = tid & 15;
    float acc[8][8];
#pragma unroll
    for (int i = 0; i < 8; i++)
#pragma unroll
        for (int j = 0; j < 8; j++) acc[i][j] = 0.f;

    for (int k0 = 0; k0 < F_FF; k0 += 16) {
        float4 a0 = *(const float4*)(Ag + (size_t)ar0 * F_FF + k0 + ak4);
        float4 a1 = *(const float4*)(Ag + (size_t)(ar0 + 64) * F_FF + k0 + ak4);
        float4 bv0 = *(const float4*)(Bg + (size_t)(k0 + br0) * D_MODEL + bc4);
        float4 bv1 = *(const float4*)(Bg + (size_t)(k0 + br0 + 8) * D_MODEL + bc4);
        __syncthreads();
        As[ak4 + 0][ar0] = a0.x; As[ak4 + 1][ar0] = a0.y;
        As[ak4 + 2][ar0] = a0.z; As[ak4 + 3][ar0] = a0.w;
        As[ak4 + 0][ar0 + 64] = a1.x; As[ak4 + 1][ar0 + 64] = a1.y;
        As[ak4 + 2][ar0 + 64] = a1.z; As[ak4 + 3][ar0 + 64] = a1.w;
        *(float4*)&Bs[br0][bc4]     = bv0;
        *(float4*)&Bs[br0 + 8][bc4] = bv1;
        __syncthreads();
#pragma unroll
        for (int kk = 0; kk < 16; kk++) {
            float af[8], bf[8];
            *(float4*)(af)     = *(const float4*)&As[kk][ty * 8];
            *(float4*)(af + 4) = *(const float4*)&As[kk][ty * 8 + 4];
            *(float4*)(bf)     = *(const float4*)&Bs[kk][tx * 8];
            *(float4*)(bf + 4) = *(const float4*)&Bs[kk][tx * 8 + 4];
#pragma unroll
            for (int i = 0; i < 8; i++)
#pragma unroll
                for (int j = 0; j < 8; j++) acc[i][j] += af[i] * bf[j];
        }
    }
    // epilogue: bias + gate-weighted scatter-add into out (<=2 adds/elem, commutative)
    const float* bp = b2g + e * D_MODEL + col0;
#pragma unroll
    for (int i = 0; i < 8; i++) {
        int r = row0 + ty * 8 + i;
        if (r < cnt) {
            int   tok = g_slot_tok[e * CAP + r];
            float w   = g_slot_w[e * CAP + r];
#pragma unroll
            for (int j = 0; j < 8; j++) {
                int c = tx * 8 + j;
                float v = (acc[i][j] + bp[c]) * w;
                atomicAdd(out + (size_t)tok * D_MODEL + col0 + c, v);
            }
        }
    }
}

// ---------------------------------------------------------------------------
extern "C" void kernel_launch(void* const* d_in, const int* in_sizes, int n_in,
                              void* d_out, int out_size) {
    const float* x   = (const float*)d_in[0];
    const float* rw  = (const float*)d_in[1];
    const float* rb  = (const float*)d_in[2];
    const float* w1  = (const float*)d_in[3];
    const float* b1  = (const float*)d_in[4];
    const float* w2  = (const float*)d_in[5];
    const float* b2  = (const float*)d_in[6];
    float* out = (float*)d_out;

    int n4 = out_size / 4;
    zero_kernel<<<(n4 + 255) / 256, 256>>>((float4*)out, n4);
    router_kernel<<<T_TOK / 8, 256>>>(x, rw, rb);
    rank_kernel<<<1, 256>>>();
    dim3 g1(F_FF / 128, CAP / 128, NE);
    gemm1_kernel<<<g1, 256>>>(x, w1, b1);
    dim3 g2(D_MODEL / 128, CAP / 128, NE);
    gemm2_kernel<<<g2, 256>>>(w2, b2, out);
}

// round 3
// speedup vs baseline: 2.5514x; 2.5514x over previous
#include <cuda_runtime.h>
#include <cstdint>
#include <math.h>

// ---------------------------------------------------------------------------
// Problem constants
// ---------------------------------------------------------------------------
#define T_TOK   8192
#define D_MODEL 1024
#define F_FF    2048
#define NE      8
#define CAP     2560
#define NA      (T_TOK * 2)

// ---------------------------------------------------------------------------
// Device scratch
// ---------------------------------------------------------------------------
__device__ float g_xt [(size_t)T_TOK * D_MODEL];       // tf32-rounded x
__device__ float g_w1t[(size_t)NE * F_FF * D_MODEL];   // w1^T [e][f][k], tf32
__device__ float g_w2t[(size_t)NE * D_MODEL * F_FF];   // w2^T [e][d][f], tf32
__device__ float g_H  [(size_t)NE * CAP * F_FF];       // gelu output, tf32-rounded
__device__ int   g_topk_i[NA];
__device__ float g_topk_w[NA];
__device__ int   g_slot_tok[NE * CAP];
__device__ float g_slot_w[NE * CAP];
__device__ int   g_cnt[NE];

// ---------------------------------------------------------------------------
// Helpers
// ---------------------------------------------------------------------------
__device__ __forceinline__ uint32_t smem_u32(const void* p) {
    uint32_t a;
    asm("{ .reg .u64 t; cvta.to.shared.u64 t, %1; cvt.u32.u64 %0, t; }" : "=r"(a) : "l"(p));
    return a;
}
__device__ __forceinline__ void cp16(uint32_t dst, const void* src) {
    asm volatile("cp.async.cg.shared.global [%0], [%1], 16;" :: "r"(dst), "l"(src));
}
__device__ __forceinline__ float to_tf32(float v) {
    uint32_t u;
    asm("cvt.rna.tf32.f32 %0, %1;" : "=r"(u) : "f"(v));
    return __uint_as_float(u);
}
// m16n8k8 tf32 mma, row.col, fp32 accumulate in place
__device__ __forceinline__ void mma8(float* d, const uint32_t* a, const uint32_t* b) {
    asm volatile(
        "mma.sync.aligned.m16n8k8.row.col.f32.tf32.tf32.f32 "
        "{%0,%1,%2,%3}, {%4,%5,%6,%7}, {%8,%9}, {%0,%1,%2,%3};"
        : "+f"(d[0]), "+f"(d[1]), "+f"(d[2]), "+f"(d[3])
        : "r"(a[0]), "r"(a[1]), "r"(a[2]), "r"(a[3]), "r"(b[0]), "r"(b[1]));
}

// Smem tile geometry: 128 rows x 32 k-floats, stride 36 (conflict-free frag LDS)
#define SROW   36
#define SSZ    (128 * SROW)             // floats per operand tile
#define STAGEF (2 * SSZ)                // A + B floats per stage
#define NSTAGE 3
#define DSMEM_BYTES (NSTAGE * STAGEF * 4)

// ---------------------------------------------------------------------------
// K0: zero output
// ---------------------------------------------------------------------------
__global__ void zero_kernel(float4* __restrict__ out, int n4) {
    int i = blockIdx.x * blockDim.x + threadIdx.x;
    if (i < n4) out[i] = make_float4(0.f, 0.f, 0.f, 0.f);
}

// ---------------------------------------------------------------------------
// K1: tf32-round x
// ---------------------------------------------------------------------------
__global__ void conv_x_kernel(const float4* __restrict__ x, float4* __restrict__ o, int n4) {
    int i = blockIdx.x * blockDim.x + threadIdx.x;
    if (i < n4) {
        float4 v = x[i];
        v.x = to_tf32(v.x); v.y = to_tf32(v.y);
        v.z = to_tf32(v.z); v.w = to_tf32(v.w);
        o[i] = v;
    }
}

// ---------------------------------------------------------------------------
// K2: transpose+convert weights: src [e][R][C] -> dst [e][C][R], tf32
// ---------------------------------------------------------------------------
__global__ void transpose_kernel(const float* __restrict__ src, float* __restrict__ dst,
                                 int R, int C) {
    __shared__ float t[32][33];
    int e = blockIdx.z;
    const float* s = src + (size_t)e * R * C;
    float* d = dst + (size_t)e * R * C;
    int c0 = blockIdx.x * 32, r0 = blockIdx.y * 32;
    int tx = threadIdx.x, ty = threadIdx.y;   // (32, 8)
#pragma unroll
    for (int j = 0; j < 32; j += 8)
        t[ty + j][tx] = s[(size_t)(r0 + ty + j) * C + c0 + tx];
    __syncthreads();
#pragma unroll
    for (int j = 0; j < 32; j += 8)
        d[(size_t)(c0 + ty + j) * R + r0 + tx] = to_tf32(t[tx][ty + j]);
}

// ---------------------------------------------------------------------------
// K3: router (one warp per token)
// ---------------------------------------------------------------------------
__global__ void router_kernel(const float* __restrict__ x,
                              const float* __restrict__ rw,
                              const float* __restrict__ rb) {
    int warp = (blockIdx.x * blockDim.x + threadIdx.x) >> 5;
    int lane = threadIdx.x & 31;
    if (warp >= T_TOK) return;
    const float* xr = x + (size_t)warp * D_MODEL;
    float acc[NE];
#pragma unroll
    for (int e = 0; e < NE; e++) acc[e] = 0.f;
    for (int d = lane; d < D_MODEL; d += 32) {
        float xv = xr[d];
        const float* w = rw + d * NE;
#pragma unroll
        for (int e = 0; e < NE; e++) acc[e] += xv * w[e];
    }
#pragma unroll
    for (int e = 0; e < NE; e++)
#pragma unroll
        for (int o = 16; o > 0; o >>= 1)
            acc[e] += __shfl_down_sync(0xffffffffu, acc[e], o);
    if (lane == 0) {
        float l[NE];
#pragma unroll
        for (int e = 0; e < NE; e++) l[e] = acc[e] + rb[e];
        float m = l[0];
#pragma unroll
        for (int e = 1; e < NE; e++) m = fmaxf(m, l[e]);
        float p[NE], s = 0.f;
#pragma unroll
        for (int e = 0; e < NE; e++) { p[e] = expf(l[e] - m); s += p[e]; }
        float inv = 1.f / s;
#pragma unroll
        for (int e = 0; e < NE; e++) p[e] *= inv;
        int i1 = 0; float p1 = p[0];
#pragma unroll
        for (int e = 1; e < NE; e++) if (p[e] > p1) { p1 = p[e]; i1 = e; }
        int i2 = -1; float p2 = -1.f;
#pragma unroll
        for (int e = 0; e < NE; e++) if (e != i1 && p[e] > p2) { p2 = p[e]; i2 = e; }
        float sum = fmaxf(p1 + p2, 1e-9f);
        g_topk_i[warp * 2 + 0] = i1;
        g_topk_i[warp * 2 + 1] = i2;
        g_topk_w[warp * 2 + 0] = p1 / sum;
        g_topk_w[warp * 2 + 1] = p2 / sum;
    }
}

// ---------------------------------------------------------------------------
// K4: stable rank / capacity / slot table (single block)
// ---------------------------------------------------------------------------
__global__ void rank_kernel() {
    __shared__ int cnts[256][NE];
    int tid = threadIdx.x;
    int base = tid * (NA / 256);
    int local[NE];
#pragma unroll
    for (int e = 0; e < NE; e++) local[e] = 0;
    for (int a = base; a < base + NA / 256; a++) local[g_topk_i[a]]++;
#pragma unroll
    for (int e = 0; e < NE; e++) cnts[tid][e] = local[e];
    __syncthreads();
    if (tid < NE) {
        int run = 0;
        for (int i = 0; i < 256; i++) { int t = cnts[i][tid]; cnts[i][tid] = run; run += t; }
        g_cnt[tid] = min(run, CAP);
    }
    __syncthreads();
#pragma unroll
    for (int e = 0; e < NE; e++) local[e] = cnts[tid][e];
    for (int a = base; a < base + NA / 256; a++) {
        int e = g_topk_i[a];
        int r = local[e]++;
        if (r < CAP) {
            g_slot_tok[e * CAP + r] = a >> 1;
            g_slot_w[e * CAP + r] = g_topk_w[a];
        }
    }
}

// ---------------------------------------------------------------------------
// GEMM core (shared between gemm1/gemm2 via an inline mainloop)
// BM=BN=128, BK=32; 8 warps as 2(M) x 4(N); warp tile 64x32 = 4x4 m16n8k8.
// acc[mt][nt][4]
// ---------------------------------------------------------------------------
struct FragState {
    const float* sA;   // smem A base (this stage)
    const float* sB;
    int warp_m, warp_n, g, t4;
};

__device__ __forceinline__ void compute_stage(const float* sA, const float* sB,
                                              int warp_m, int warp_n, int g, int t4,
                                              float acc[4][4][4]) {
#pragma unroll
    for (int j = 0; j < 4; j++) {
        uint32_t af[4][4], bf[4][2];
#pragma unroll
        for (int mt = 0; mt < 4; mt++) {
            const float* p = sA + (warp_m + mt * 16 + g) * SROW + j * 8 + t4;
            af[mt][0] = __float_as_uint(p[0]);
            af[mt][1] = __float_as_uint(p[8 * SROW]);
            af[mt][2] = __float_as_uint(p[4]);
            af[mt][3] = __float_as_uint(p[8 * SROW + 4]);
        }
#pragma unroll
        for (int nt = 0; nt < 4; nt++) {
            const float* p = sB + (warp_n + nt * 8 + g) * SROW + j * 8 + t4;
            bf[nt][0] = __float_as_uint(p[0]);
            bf[nt][1] = __float_as_uint(p[4]);
        }
#pragma unroll
        for (int mt = 0; mt < 4; mt++)
#pragma unroll
            for (int nt = 0; nt < 4; nt++)
                mma8(acc[mt][nt], af[mt], bf[nt]);
    }
}

// K5: GEMM1 + bias + gelu -> g_H
__global__ __launch_bounds__(256, 1)
void gemm1_kernel(const float* __restrict__ b1) {
    int e = blockIdx.z;
    int cnt = g_cnt[e];
    int row0 = blockIdx.y * 128;
    if (row0 >= cnt) return;
    int col0 = blockIdx.x * 128;

    extern __shared__ float smem[];
    uint32_t sb = smem_u32(smem);

    int tid = threadIdx.x;
    int wid = tid >> 5, lane = tid & 31;
    int warp_m = (wid >> 2) * 64, warp_n = (wid & 3) * 32;
    int g = lane >> 2, t4 = lane & 3;

    // loader: thread covers rows rA+32q (q=0..3), 16B chunk c4
    int rA = tid >> 3;
    int c4 = (tid & 7) * 4;
    const float* aP[4];
    const float* bP[4];
    uint32_t stA[4], stB[4];
    const float* w1e = g_w1t + (size_t)e * F_FF * D_MODEL;
#pragma unroll
    for (int q = 0; q < 4; q++) {
        int r = rA + 32 * q;
        int grow = row0 + r;
        int tok = (grow < cnt) ? g_slot_tok[e * CAP + grow] : 0;
        aP[q] = g_xt + (size_t)tok * D_MODEL + c4;
        bP[q] = w1e + (size_t)(col0 + r) * D_MODEL + c4;
        stA[q] = sb + (uint32_t)(r * SROW + c4) * 4u;
        stB[q] = sb + (uint32_t)(SSZ + r * SROW + c4) * 4u;
    }

    float acc[4][4][4];
#pragma unroll
    for (int mt = 0; mt < 4; mt++)
#pragma unroll
        for (int nt = 0; nt < 4; nt++)
#pragma unroll
            for (int k = 0; k < 4; k++) acc[mt][nt][k] = 0.f;

    const int NCH = D_MODEL / 32;   // 32

    // prologue: chunks 0,1 into stages 0,1
#pragma unroll
    for (int c = 0; c < 2; c++) {
        uint32_t so = (uint32_t)(c * STAGEF * 4);
#pragma unroll
        for (int q = 0; q < 4; q++) {
            cp16(stA[q] + so, aP[q]); aP[q] += 32;
            cp16(stB[q] + so, bP[q]); bP[q] += 32;
        }
        asm volatile("cp.async.commit_group;" ::: "memory");
    }

    for (int i = 0; i < NCH; i++) {
        if (i + 2 < NCH) {
            uint32_t so = (uint32_t)(((i + 2) % NSTAGE) * STAGEF * 4);
#pragma unroll
            for (int q = 0; q < 4; q++) {
                cp16(stA[q] + so, aP[q]); aP[q] += 32;
                cp16(stB[q] + so, bP[q]); bP[q] += 32;
            }
            asm volatile("cp.async.commit_group;" ::: "memory");
            asm volatile("cp.async.wait_group 2;" ::: "memory");
        } else if (i + 1 < NCH) {
            asm volatile("cp.async.wait_group 1;" ::: "memory");
        } else {
            asm volatile("cp.async.wait_group 0;" ::: "memory");
        }
        __syncthreads();
        const float* sA = smem + (i % NSTAGE) * STAGEF;
        compute_stage(sA, sA + SSZ, warp_m, warp_n, g, t4, acc);
        __syncthreads();
    }

    // epilogue: bias + gelu + tf32 round -> H (float2 stores)
    const float* bp = b1 + e * F_FF + col0;
#pragma unroll
    for (int mt = 0; mt < 4; mt++) {
#pragma unroll
        for (int h = 0; h < 2; h++) {
            int r = row0 + warp_m + mt * 16 + g + h * 8;
            float* Hrow = g_H + ((size_t)e * CAP + r) * F_FF + col0;
#pragma unroll
            for (int nt = 0; nt < 4; nt++) {
                int c = warp_n + nt * 8 + 2 * t4;
                float v0 = acc[mt][nt][2 * h + 0] + bp[c];
                float v1 = acc[mt][nt][2 * h + 1] + bp[c + 1];
                v0 = 0.5f * v0 * (1.f + erff(v0 * 0.70710678118654752f));
                v1 = 0.5f * v1 * (1.f + erff(v1 * 0.70710678118654752f));
                float2 o = make_float2(to_tf32(v0), to_tf32(v1));
                *(float2*)(Hrow + c) = o;
            }
        }
    }
}

// K6: GEMM2 + bias + gated atomic scatter -> out
__global__ __launch_bounds__(256, 1)
void gemm2_kernel(const float* __restrict__ b2, float* __restrict__ out) {
    int e = blockIdx.z;
    int cnt = g_cnt[e];
    int row0 = blockIdx.y * 128;
    if (row0 >= cnt) return;
    int col0 = blockIdx.x * 128;

    extern __shared__ float smem[];
    uint32_t sb = smem_u32(smem);

    int tid = threadIdx.x;
    int wid = tid >> 5, lane = tid & 31;
    int warp_m = (wid >> 2) * 64, warp_n = (wid & 3) * 32;
    int g = lane >> 2, t4 = lane & 3;

    int rA = tid >> 3;
    int c4 = (tid & 7) * 4;
    const float* aP[4];
    const float* bP[4];
    uint32_t stA[4], stB[4];
    const float* w2e = g_w2t + (size_t)e * D_MODEL * F_FF;
    const float* He = g_H + (size_t)e * CAP * F_FF;
#pragma unroll
    for (int q = 0; q < 4; q++) {
        int r = rA + 32 * q;
        aP[q] = He + (size_t)(row0 + r) * F_FF + c4;
        bP[q] = w2e + (size_t)(col0 + r) * F_FF + c4;
        stA[q] = sb + (uint32_t)(r * SROW + c4) * 4u;
        stB[q] = sb + (uint32_t)(SSZ + r * SROW + c4) * 4u;
    }

    float acc[4][4][4];
#pragma unroll
    for (int mt = 0; mt < 4; mt++)
#pragma unroll
        for (int nt = 0; nt < 4; nt++)
#pragma unroll
            for (int k = 0; k < 4; k++) acc[mt][nt][k] = 0.f;

    const int NCH = F_FF / 32;   // 64

#pragma unroll
    for (int c = 0; c < 2; c++) {
        uint32_t so = (uint32_t)(c * STAGEF * 4);
#pragma unroll
        for (int q = 0; q < 4; q++) {
            cp16(stA[q] + so, aP[q]); aP[q] += 32;
            cp16(stB[q] + so, bP[q]); bP[q] += 32;
        }
        asm volatile("cp.async.commit_group;" ::: "memory");
    }

    for (int i = 0; i < NCH; i++) {
        if (i + 2 < NCH) {
            uint32_t so = (uint32_t)(((i + 2) % NSTAGE) * STAGEF * 4);
#pragma unroll
            for (int q = 0; q < 4; q++) {
                cp16(stA[q] + so, aP[q]); aP[q] += 32;
                cp16(stB[q] + so, bP[q]); bP[q] += 32;
            }
            asm volatile("cp.async.commit_group;" ::: "memory");
            asm volatile("cp.async.wait_group 2;" ::: "memory");
        } else if (i + 1 < NCH) {
            asm volatile("cp.async.wait_group 1;" ::: "memory");
        } else {
            asm volatile("cp.async.wait_group 0;" ::: "memory");
        }
        __syncthreads();
        const float* sA = smem + (i % NSTAGE) * STAGEF;
        compute_stage(sA, sA + SSZ, warp_m, warp_n, g, t4, acc);
        __syncthreads();
    }

    // epilogue: bias + gate + atomic scatter
    const float* bp = b2 + e * D_MODEL + col0;
#pragma unroll
    for (int mt = 0; mt < 4; mt++) {
#pragma unroll
        for (int h = 0; h < 2; h++) {
            int r = row0 + warp_m + mt * 16 + g + h * 8;
            if (r < cnt) {
                int   tok = g_slot_tok[e * CAP + r];
                float w   = g_slot_w[e * CAP + r];
                float* orow = out + (size_t)tok * D_MODEL + col0;
#pragma unroll
                for (int nt = 0; nt < 4; nt++) {
                    int c = warp_n + nt * 8 + 2 * t4;
                    atomicAdd(orow + c,     (acc[mt][nt][2 * h + 0] + bp[c])     * w);
                    atomicAdd(orow + c + 1, (acc[mt][nt][2 * h + 1] + bp[c + 1]) * w);
                }
            }
        }
    }
}

// ---------------------------------------------------------------------------
extern "C" void kernel_launch(void* const* d_in, const int* in_sizes, int n_in,
                              void* d_out, int out_size) {
    const float* x  = (const float*)d_in[0];
    const float* rw = (const float*)d_in[1];
    const float* rb = (const float*)d_in[2];
    const float* w1 = (const float*)d_in[3];
    const float* b1 = (const float*)d_in[4];
    const float* w2 = (const float*)d_in[5];
    const float* b2 = (const float*)d_in[6];
    float* out = (float*)d_out;

    cudaFuncSetAttribute(gemm1_kernel, cudaFuncAttributeMaxDynamicSharedMemorySize, DSMEM_BYTES);
    cudaFuncSetAttribute(gemm2_kernel, cudaFuncAttributeMaxDynamicSharedMemorySize, DSMEM_BYTES);

    int n4 = out_size / 4;
    zero_kernel<<<(n4 + 255) / 256, 256>>>((float4*)out, n4);

    {   // tf32-round x
        float* xt;
        cudaGetSymbolAddress((void**)&xt, g_xt);
        int m4 = T_TOK * D_MODEL / 4;
        conv_x_kernel<<<(m4 + 255) / 256, 256>>>((const float4*)x, (float4*)xt, m4);
    }
    {   // transpose + convert weights
        float *w1t, *w2t;
        cudaGetSymbolAddress((void**)&w1t, g_w1t);
        cudaGetSymbolAddress((void**)&w2t, g_w2t);
        dim3 b(32, 8);
        dim3 g1(F_FF / 32, D_MODEL / 32, NE);   // w1: R=D, C=F
        transpose_kernel<<<g1, b>>>(w1, w1t, D_MODEL, F_FF);
        dim3 g2(D_MODEL / 32, F_FF / 32, NE);   // w2: R=F, C=D
        transpose_kernel<<<g2, b>>>(w2, w2t, F_FF, D_MODEL);
    }

    router_kernel<<<T_TOK / 8, 256>>>(x, rw, rb);
    rank_kernel<<<1, 256>>>();

    dim3 gg1(F_FF / 128, CAP / 128, NE);
    gemm1_kernel<<<gg1, 256, DSMEM_BYTES>>>(b1);
    dim3 gg2(D_MODEL / 128, CAP / 128, NE);
    gemm2_kernel<<<gg2, 256, DSMEM_BYTES>>>(b2, out);
}

// round 4
// speedup vs baseline: 2.5927x; 1.0162x over previous
#include <cuda_runtime.h>
#include <cstdint>
#include <math.h>

// ---------------------------------------------------------------------------
// Problem constants
// ---------------------------------------------------------------------------
#define T_TOK   8192
#define D_MODEL 1024
#define F_FF    2048
#define NE      8
#define CAP     2560
#define NA      (T_TOK * 2)

// ---------------------------------------------------------------------------
// Device scratch
// ---------------------------------------------------------------------------
__device__ float g_xt [(size_t)T_TOK * D_MODEL];       // tf32-rounded x
__device__ float g_w1t[(size_t)NE * F_FF * D_MODEL];   // w1^T [e][f][k], tf32
__device__ float g_w2t[(size_t)NE * D_MODEL * F_FF];   // w2^T [e][d][f], tf32
__device__ float g_H  [(size_t)NE * CAP * F_FF];       // gelu output, tf32-rounded
__device__ int   g_topk_i[NA];
__device__ float g_topk_w[NA];
__device__ int   g_slot_tok[NE * CAP];
__device__ float g_slot_w[NE * CAP];
__device__ int   g_cnt[NE];

// ---------------------------------------------------------------------------
// Helpers
// ---------------------------------------------------------------------------
__device__ __forceinline__ uint32_t smem_u32(const void* p) {
    uint32_t a;
    asm("{ .reg .u64 t; cvta.to.shared.u64 t, %1; cvt.u32.u64 %0, t; }" : "=r"(a) : "l"(p));
    return a;
}
__device__ __forceinline__ void cp16(uint32_t dst, const void* src) {
    asm volatile("cp.async.cg.shared.global [%0], [%1], 16;" :: "r"(dst), "l"(src));
}
__device__ __forceinline__ float to_tf32(float v) {
    uint32_t u;
    asm("cvt.rna.tf32.f32 %0, %1;" : "=r"(u) : "f"(v));
    return __uint_as_float(u);
}
// m16n8k8 tf32 mma, row.col, fp32 accumulate in place
__device__ __forceinline__ void mma8(float* d, const uint32_t* a, const uint32_t* b) {
    asm volatile(
        "mma.sync.aligned.m16n8k8.row.col.f32.tf32.tf32.f32 "
        "{%0,%1,%2,%3}, {%4,%5,%6,%7}, {%8,%9}, {%0,%1,%2,%3};"
        : "+f"(d[0]), "+f"(d[1]), "+f"(d[2]), "+f"(d[3])
        : "r"(a[0]), "r"(a[1]), "r"(a[2]), "r"(a[3]), "r"(b[0]), "r"(b[1]));
}

// Smem geometry: stride 36 floats per 32-k row (conflict-free fragment LDS)
#define SROW   36
#define BM     256
#define BN     128
#define ASZ    (BM * SROW)              // A floats per stage
#define BSZ    (BN * SROW)              // B floats per stage
#define STAGEF (ASZ + BSZ)
#define NSTAGE 3
#define DSMEM_BYTES (NSTAGE * STAGEF * 4)

// ---------------------------------------------------------------------------
// K0: zero output
// ---------------------------------------------------------------------------
__global__ void zero_kernel(float4* __restrict__ out, int n4) {
    int i = blockIdx.x * blockDim.x + threadIdx.x;
    if (i < n4) out[i] = make_float4(0.f, 0.f, 0.f, 0.f);
}

// ---------------------------------------------------------------------------
// K1: tf32-round x
// ---------------------------------------------------------------------------
__global__ void conv_x_kernel(const float4* __restrict__ x, float4* __restrict__ o, int n4) {
    int i = blockIdx.x * blockDim.x + threadIdx.x;
    if (i < n4) {
        float4 v = x[i];
        v.x = to_tf32(v.x); v.y = to_tf32(v.y);
        v.z = to_tf32(v.z); v.w = to_tf32(v.w);
        o[i] = v;
    }
}

// ---------------------------------------------------------------------------
// K2: transpose+convert weights: src [e][R][C] -> dst [e][C][R], tf32
// ---------------------------------------------------------------------------
__global__ void transpose_kernel(const float* __restrict__ src, float* __restrict__ dst,
                                 int R, int C) {
    __shared__ float t[32][33];
    int e = blockIdx.z;
    const float* s = src + (size_t)e * R * C;
    float* d = dst + (size_t)e * R * C;
    int c0 = blockIdx.x * 32, r0 = blockIdx.y * 32;
    int tx = threadIdx.x, ty = threadIdx.y;   // (32, 8)
#pragma unroll
    for (int j = 0; j < 32; j += 8)
        t[ty + j][tx] = s[(size_t)(r0 + ty + j) * C + c0 + tx];
    __syncthreads();
#pragma unroll
    for (int j = 0; j < 32; j += 8)
        d[(size_t)(c0 + ty + j) * R + r0 + tx] = to_tf32(t[tx][ty + j]);
}

// ---------------------------------------------------------------------------
// K3: router (one warp per token)
// ---------------------------------------------------------------------------
__global__ void router_kernel(const float* __restrict__ x,
                              const float* __restrict__ rw,
                              const float* __restrict__ rb) {
    int warp = (blockIdx.x * blockDim.x + threadIdx.x) >> 5;
    int lane = threadIdx.x & 31;
    if (warp >= T_TOK) return;
    const float* xr = x + (size_t)warp * D_MODEL;
    float acc[NE];
#pragma unroll
    for (int e = 0; e < NE; e++) acc[e] = 0.f;
    for (int d = lane; d < D_MODEL; d += 32) {
        float xv = xr[d];
        const float* w = rw + d * NE;
#pragma unroll
        for (int e = 0; e < NE; e++) acc[e] += xv * w[e];
    }
#pragma unroll
    for (int e = 0; e < NE; e++)
#pragma unroll
        for (int o = 16; o > 0; o >>= 1)
            acc[e] += __shfl_down_sync(0xffffffffu, acc[e], o);
    if (lane == 0) {
        float l[NE];
#pragma unroll
        for (int e = 0; e < NE; e++) l[e] = acc[e] + rb[e];
        float m = l[0];
#pragma unroll
        for (int e = 1; e < NE; e++) m = fmaxf(m, l[e]);
        float p[NE], s = 0.f;
#pragma unroll
        for (int e = 0; e < NE; e++) { p[e] = expf(l[e] - m); s += p[e]; }
        float inv = 1.f / s;
#pragma unroll
        for (int e = 0; e < NE; e++) p[e] *= inv;
        int i1 = 0; float p1 = p[0];
#pragma unroll
        for (int e = 1; e < NE; e++) if (p[e] > p1) { p1 = p[e]; i1 = e; }
        int i2 = -1; float p2 = -1.f;
#pragma unroll
        for (int e = 0; e < NE; e++) if (e != i1 && p[e] > p2) { p2 = p[e]; i2 = e; }
        float sum = fmaxf(p1 + p2, 1e-9f);
        g_topk_i[warp * 2 + 0] = i1;
        g_topk_i[warp * 2 + 1] = i2;
        g_topk_w[warp * 2 + 0] = p1 / sum;
        g_topk_w[warp * 2 + 1] = p2 / sum;
    }
}

// ---------------------------------------------------------------------------
// K4: stable rank / capacity / slot table (single block)
// ---------------------------------------------------------------------------
__global__ void rank_kernel() {
    __shared__ int cnts[256][NE];
    int tid = threadIdx.x;
    int base = tid * (NA / 256);
    int local[NE];
#pragma unroll
    for (int e = 0; e < NE; e++) local[e] = 0;
    for (int a = base; a < base + NA / 256; a++) local[g_topk_i[a]]++;
#pragma unroll
    for (int e = 0; e < NE; e++) cnts[tid][e] = local[e];
    __syncthreads();
    if (tid < NE) {
        int run = 0;
        for (int i = 0; i < 256; i++) { int t = cnts[i][tid]; cnts[i][tid] = run; run += t; }
        g_cnt[tid] = min(run, CAP);
    }
    __syncthreads();
#pragma unroll
    for (int e = 0; e < NE; e++) local[e] = cnts[tid][e];
    for (int a = base; a < base + NA / 256; a++) {
        int e = g_topk_i[a];
        int r = local[e]++;
        if (r < CAP) {
            g_slot_tok[e * CAP + r] = a >> 1;
            g_slot_w[e * CAP + r] = g_topk_w[a];
        }
    }
}

// ---------------------------------------------------------------------------
// GEMM core: BM=256, BN=128, BK=32. 8 warps as 4(M) x 2(N); warp tile 64x64
// = 4x8 m16n8k8 tiles. acc[4][8][4]. LDS:MMA = 1.0 per j-step.
// ---------------------------------------------------------------------------
__device__ __forceinline__ void compute_stage(const float* sA, const float* sB,
                                              int warp_m, int warp_n, int g, int t4,
                                              float acc[4][8][4]) {
#pragma unroll
    for (int j = 0; j < 4; j++) {
        uint32_t af[4][4], bf[8][2];
#pragma unroll
        for (int mt = 0; mt < 4; mt++) {
            const float* p = sA + (warp_m + mt * 16 + g) * SROW + j * 8 + t4;
            af[mt][0] = __float_as_uint(p[0]);
            af[mt][1] = __float_as_uint(p[8 * SROW]);
            af[mt][2] = __float_as_uint(p[4]);
            af[mt][3] = __float_as_uint(p[8 * SROW + 4]);
        }
#pragma unroll
        for (int nt = 0; nt < 8; nt++) {
            const float* p = sB + (warp_n + nt * 8 + g) * SROW + j * 8 + t4;
            bf[nt][0] = __float_as_uint(p[0]);
            bf[nt][1] = __float_as_uint(p[4]);
        }
#pragma unroll
        for (int mt = 0; mt < 4; mt++)
#pragma unroll
            for (int nt = 0; nt < 8; nt++)
                mma8(acc[mt][nt], af[mt], bf[nt]);
    }
}

// K5: GEMM1 + bias + gelu -> g_H
__global__ __launch_bounds__(256, 1)
void gemm1_kernel(const float* __restrict__ b1) {
    int e = blockIdx.z;
    int cnt = g_cnt[e];
    int row0 = blockIdx.y * BM;
    if (row0 >= cnt) return;
    int col0 = blockIdx.x * BN;

    extern __shared__ float smem[];
    uint32_t sb = smem_u32(smem);

    int tid = threadIdx.x;
    int wid = tid >> 5, lane = tid & 31;
    int warp_m = (wid >> 1) * 64, warp_n = (wid & 1) * 64;
    int g = lane >> 2, t4 = lane & 3;

    // loader: thread covers row (tid>>3)+32q, 16B chunk (tid&7)*4
    int rA = tid >> 3;
    int c4 = (tid & 7) * 4;
    const float* aP[8];
    const float* bP[4];
    uint32_t stA[8], stB[4];
    const float* w1e = g_w1t + (size_t)e * F_FF * D_MODEL;
#pragma unroll
    for (int q = 0; q < 8; q++) {
        int r = rA + 32 * q;
        int grow = row0 + r;
        int tok = (grow < cnt) ? g_slot_tok[e * CAP + grow] : 0;
        aP[q] = g_xt + (size_t)tok * D_MODEL + c4;
        stA[q] = sb + (uint32_t)(r * SROW + c4) * 4u;
    }
#pragma unroll
    for (int q = 0; q < 4; q++) {
        int r = rA + 32 * q;
        bP[q] = w1e + (size_t)(col0 + r) * D_MODEL + c4;
        stB[q] = sb + (uint32_t)(ASZ + r * SROW + c4) * 4u;
    }

    float acc[4][8][4];
#pragma unroll
    for (int mt = 0; mt < 4; mt++)
#pragma unroll
        for (int nt = 0; nt < 8; nt++)
#pragma unroll
            for (int k = 0; k < 4; k++) acc[mt][nt][k] = 0.f;

    const int NCH = D_MODEL / 32;   // 32

#pragma unroll
    for (int c = 0; c < 2; c++) {
        uint32_t so = (uint32_t)(c * STAGEF * 4);
#pragma unroll
        for (int q = 0; q < 8; q++) { cp16(stA[q] + so, aP[q]); aP[q] += 32; }
#pragma unroll
        for (int q = 0; q < 4; q++) { cp16(stB[q] + so, bP[q]); bP[q] += 32; }
        asm volatile("cp.async.commit_group;" ::: "memory");
    }

    for (int i = 0; i < NCH; i++) {
        if (i + 2 < NCH) {
            uint32_t so = (uint32_t)(((i + 2) % NSTAGE) * STAGEF * 4);
#pragma unroll
            for (int q = 0; q < 8; q++) { cp16(stA[q] + so, aP[q]); aP[q] += 32; }
#pragma unroll
            for (int q = 0; q < 4; q++) { cp16(stB[q] + so, bP[q]); bP[q] += 32; }
            asm volatile("cp.async.commit_group;" ::: "memory");
            asm volatile("cp.async.wait_group 2;" ::: "memory");
        } else if (i + 1 < NCH) {
            asm volatile("cp.async.wait_group 1;" ::: "memory");
        } else {
            asm volatile("cp.async.wait_group 0;" ::: "memory");
        }
        __syncthreads();
        const float* sA = smem + (i % NSTAGE) * STAGEF;
        compute_stage(sA, sA + ASZ, warp_m, warp_n, g, t4, acc);
        __syncthreads();
    }

    // epilogue: bias + gelu + tf32 round -> H (float2 stores)
    const float* bp = b1 + e * F_FF + col0;
#pragma unroll
    for (int mt = 0; mt < 4; mt++) {
#pragma unroll
        for (int h = 0; h < 2; h++) {
            int r = row0 + warp_m + mt * 16 + g + h * 8;
            float* Hrow = g_H + ((size_t)e * CAP + r) * F_FF + col0;
#pragma unroll
            for (int nt = 0; nt < 8; nt++) {
                int c = warp_n + nt * 8 + 2 * t4;
                float v0 = acc[mt][nt][2 * h + 0] + bp[c];
                float v1 = acc[mt][nt][2 * h + 1] + bp[c + 1];
                v0 = 0.5f * v0 * (1.f + erff(v0 * 0.70710678118654752f));
                v1 = 0.5f * v1 * (1.f + erff(v1 * 0.70710678118654752f));
                float2 o = make_float2(to_tf32(v0), to_tf32(v1));
                *(float2*)(Hrow + c) = o;
            }
        }
    }
}

// K6: GEMM2 + bias + gated atomic scatter -> out
__global__ __launch_bounds__(256, 1)
void gemm2_kernel(const float* __restrict__ b2, float* __restrict__ out) {
    int e = blockIdx.z;
    int cnt = g_cnt[e];
    int row0 = blockIdx.y * BM;
    if (row0 >= cnt) return;
    int col0 = blockIdx.x * BN;

    extern __shared__ float smem[];
    uint32_t sb = smem_u32(smem);

    int tid = threadIdx.x;
    int wid = tid >> 5, lane = tid & 31;
    int warp_m = (wid >> 1) * 64, warp_n = (wid & 1) * 64;
    int g = lane >> 2, t4 = lane & 3;

    int rA = tid >> 3;
    int c4 = (tid & 7) * 4;
    const float* aP[8];
    const float* bP[4];
    uint32_t stA[8], stB[4];
    const float* w2e = g_w2t + (size_t)e * D_MODEL * F_FF;
    const float* He = g_H + (size_t)e * CAP * F_FF;
#pragma unroll
    for (int q = 0; q < 8; q++) {
        int r = rA + 32 * q;
        aP[q] = He + (size_t)(row0 + r) * F_FF + c4;
        stA[q] = sb + (uint32_t)(r * SROW + c4) * 4u;
    }
#pragma unroll
    for (int q = 0; q < 4; q++) {
        int r = rA + 32 * q;
        bP[q] = w2e + (size_t)(col0 + r) * F_FF + c4;
        stB[q] = sb + (uint32_t)(ASZ + r * SROW + c4) * 4u;
    }

    float acc[4][8][4];
#pragma unroll
    for (int mt = 0; mt < 4; mt++)
#pragma unroll
        for (int nt = 0; nt < 8; nt++)
#pragma unroll
            for (int k = 0; k < 4; k++) acc[mt][nt][k] = 0.f;

    const int NCH = F_FF / 32;   // 64

#pragma unroll
    for (int c = 0; c < 2; c++) {
        uint32_t so = (uint32_t)(c * STAGEF * 4);
#pragma unroll
        for (int q = 0; q < 8; q++) { cp16(stA[q] + so, aP[q]); aP[q] += 32; }
#pragma unroll
        for (int q = 0; q < 4; q++) { cp16(stB[q] + so, bP[q]); bP[q] += 32; }
        asm volatile("cp.async.commit_group;" ::: "memory");
    }

    for (int i = 0; i < NCH; i++) {
        if (i + 2 < NCH) {
            uint32_t so = (uint32_t)(((i + 2) % NSTAGE) * STAGEF * 4);
#pragma unroll
            for (int q = 0; q < 8; q++) { cp16(stA[q] + so, aP[q]); aP[q] += 32; }
#pragma unroll
            for (int q = 0; q < 4; q++) { cp16(stB[q] + so, bP[q]); bP[q] += 32; }
            asm volatile("cp.async.commit_group;" ::: "memory");
            asm volatile("cp.async.wait_group 2;" ::: "memory");
        } else if (i + 1 < NCH) {
            asm volatile("cp.async.wait_group 1;" ::: "memory");
        } else {
            asm volatile("cp.async.wait_group 0;" ::: "memory");
        }
        __syncthreads();
        const float* sA = smem + (i % NSTAGE) * STAGEF;
        compute_stage(sA, sA + ASZ, warp_m, warp_n, g, t4, acc);
        __syncthreads();
    }

    // epilogue: bias + gate + atomic scatter
    const float* bp = b2 + e * D_MODEL + col0;
#pragma unroll
    for (int mt = 0; mt < 4; mt++) {
#pragma unroll
        for (int h = 0; h < 2; h++) {
            int r = row0 + warp_m + mt * 16 + g + h * 8;
            if (r < cnt) {
                int   tok = g_slot_tok[e * CAP + r];
                float w   = g_slot_w[e * CAP + r];
                float* orow = out + (size_t)tok * D_MODEL + col0;
#pragma unroll
                for (int nt = 0; nt < 8; nt++) {
                    int c = warp_n + nt * 8 + 2 * t4;
                    atomicAdd(orow + c,     (acc[mt][nt][2 * h + 0] + bp[c])     * w);
                    atomicAdd(orow + c + 1, (acc[mt][nt][2 * h + 1] + bp[c + 1]) * w);
                }
            }
        }
    }
}

// ---------------------------------------------------------------------------
extern "C" void kernel_launch(void* const* d_in, const int* in_sizes, int n_in,
                              void* d_out, int out_size) {
    const float* x  = (const float*)d_in[0];
    const float* rw = (const float*)d_in[1];
    const float* rb = (const float*)d_in[2];
    const float* w1 = (const float*)d_in[3];
    const float* b1 = (const float*)d_in[4];
    const float* w2 = (const float*)d_in[5];
    const float* b2 = (const float*)d_in[6];
    float* out = (float*)d_out;

    cudaFuncSetAttribute(gemm1_kernel, cudaFuncAttributeMaxDynamicSharedMemorySize, DSMEM_BYTES);
    cudaFuncSetAttribute(gemm2_kernel, cudaFuncAttributeMaxDynamicSharedMemorySize, DSMEM_BYTES);

    int n4 = out_size / 4;
    zero_kernel<<<(n4 + 255) / 256, 256>>>((float4*)out, n4);

    {   // tf32-round x
        float* xt;
        cudaGetSymbolAddress((void**)&xt, g_xt);
        int m4 = T_TOK * D_MODEL / 4;
        conv_x_kernel<<<(m4 + 255) / 256, 256>>>((const float4*)x, (float4*)xt, m4);
    }
    {   // transpose + convert weights
        float *w1t, *w2t;
        cudaGetSymbolAddress((void**)&w1t, g_w1t);
        cudaGetSymbolAddress((void**)&w2t, g_w2t);
        dim3 b(32, 8);
        dim3 g1(F_FF / 32, D_MODEL / 32, NE);   // w1: R=D, C=F
        transpose_kernel<<<g1, b>>>(w1, w1t, D_MODEL, F_FF);
        dim3 g2(D_MODEL / 32, F_FF / 32, NE);   // w2: R=F, C=D
        transpose_kernel<<<g2, b>>>(w2, w2t, F_FF, D_MODEL);
    }

    router_kernel<<<T_TOK / 8, 256>>>(x, rw, rb);
    rank_kernel<<<1, 256>>>();

    dim3 gg1(F_FF / BN, CAP / BM, NE);
    gemm1_kernel<<<gg1, 256, DSMEM_BYTES>>>(b1);
    dim3 gg2(D_MODEL / BN, CAP / BM, NE);
    gemm2_kernel<<<gg2, 256, DSMEM_BYTES>>>(b2, out);
}

// round 5
// speedup vs baseline: 4.7224x; 1.8214x over previous
#include <cuda_runtime.h>
#include <cuda_fp16.h>
#include <cstdint>
#include <math.h>

// ---------------------------------------------------------------------------
// Problem constants
// ---------------------------------------------------------------------------
#define T_TOK   8192
#define D_MODEL 1024
#define F_FF    2048
#define NE      8
#define CAP     2560
#define NA      (T_TOK * 2)

// ---------------------------------------------------------------------------
// Device scratch
// ---------------------------------------------------------------------------
__device__ __half g_xh [(size_t)T_TOK * D_MODEL];       // fp16 x
__device__ __half g_w1h[(size_t)NE * F_FF * D_MODEL];   // w1^T [e][f][k] fp16
__device__ __half g_w2h[(size_t)NE * D_MODEL * F_FF];   // w2^T [e][d][f] fp16
__device__ __half g_Hh [(size_t)NE * CAP * F_FF];       // gelu output fp16
__device__ int    g_topk_i[NA];
__device__ float  g_topk_w[NA];
__device__ int    g_slot_tok[NE * CAP];
__device__ float  g_slot_w[NE * CAP];
__device__ int    g_cnt[NE];

// ---------------------------------------------------------------------------
// Helpers
// ---------------------------------------------------------------------------
__device__ __forceinline__ uint32_t smem_u32(const void* p) {
    uint32_t a;
    asm("{ .reg .u64 t; cvta.to.shared.u64 t, %1; cvt.u32.u64 %0, t; }" : "=r"(a) : "l"(p));
    return a;
}
__device__ __forceinline__ void cp16(uint32_t dst, const void* src) {
    asm volatile("cp.async.cg.shared.global [%0], [%1], 16;" :: "r"(dst), "l"(src));
}
// fp16 m16n8k16 mma, row.col, fp32 accumulate in place
__device__ __forceinline__ void mma16(float* d, const uint32_t* a, const uint32_t* b) {
    asm volatile(
        "mma.sync.aligned.m16n8k16.row.col.f32.f16.f16.f32 "
        "{%0,%1,%2,%3}, {%4,%5,%6,%7}, {%8,%9}, {%0,%1,%2,%3};"
        : "+f"(d[0]), "+f"(d[1]), "+f"(d[2]), "+f"(d[3])
        : "r"(a[0]), "r"(a[1]), "r"(a[2]), "r"(a[3]), "r"(b[0]), "r"(b[1]));
}
#define LDSM4(r0, r1, r2, r3, a) \
    asm volatile("ldmatrix.sync.aligned.m8n8.x4.shared.b16 {%0,%1,%2,%3}, [%4];" \
                 : "=r"(r0), "=r"(r1), "=r"(r2), "=r"(r3) : "r"(a))

// Tile geometry: BM=256, BN=128, BK=64 halves (128B rows, XOR-swizzled chunks)
#define BM      256
#define BN      128
#define ASTG    32768                    // A bytes per stage (256*128)
#define BSTG    16384                    // B bytes per stage (128*128)
#define STAGEB  (ASTG + BSTG)            // 48 KB
#define NSTAGE  3
#define DSMEM_BYTES (NSTAGE * STAGEB)    // 144 KB

// ---------------------------------------------------------------------------
// K0: zero output
// ---------------------------------------------------------------------------
__global__ void zero_kernel(float4* __restrict__ out, int n4) {
    int i = blockIdx.x * blockDim.x + threadIdx.x;
    if (i < n4) out[i] = make_float4(0.f, 0.f, 0.f, 0.f);
}

// ---------------------------------------------------------------------------
// K1: x -> fp16
// ---------------------------------------------------------------------------
__global__ void conv_x_kernel(const float2* __restrict__ x, __half2* __restrict__ o, int n2) {
    int i = blockIdx.x * blockDim.x + threadIdx.x;
    if (i < n2) {
        float2 v = x[i];
        o[i] = __floats2half2_rn(v.x, v.y);
    }
}

// ---------------------------------------------------------------------------
// K2: transpose+convert weights: src [e][R][C] fp32 -> dst [e][C][R] fp16
// ---------------------------------------------------------------------------
__global__ void transpose_kernel(const float* __restrict__ src, __half* __restrict__ dst,
                                 int R, int C) {
    __shared__ float t[32][33];
    int e = blockIdx.z;
    const float* s = src + (size_t)e * R * C;
    __half* d = dst + (size_t)e * R * C;
    int c0 = blockIdx.x * 32, r0 = blockIdx.y * 32;
    int tx = threadIdx.x, ty = threadIdx.y;   // (32, 8)
#pragma unroll
    for (int j = 0; j < 32; j += 8)
        t[ty + j][tx] = s[(size_t)(r0 + ty + j) * C + c0 + tx];
    __syncthreads();
#pragma unroll
    for (int j = 0; j < 32; j += 8)
        d[(size_t)(c0 + ty + j) * R + r0 + tx] = __float2half_rn(t[tx][ty + j]);
}

// ---------------------------------------------------------------------------
// K3: router (one warp per token)
// ---------------------------------------------------------------------------
__global__ void router_kernel(const float* __restrict__ x,
                              const float* __restrict__ rw,
                              const float* __restrict__ rb) {
    int warp = (blockIdx.x * blockDim.x + threadIdx.x) >> 5;
    int lane = threadIdx.x & 31;
    if (warp >= T_TOK) return;
    const float* xr = x + (size_t)warp * D_MODEL;
    float acc[NE];
#pragma unroll
    for (int e = 0; e < NE; e++) acc[e] = 0.f;
    for (int d = lane; d < D_MODEL; d += 32) {
        float xv = xr[d];
        const float* w = rw + d * NE;
#pragma unroll
        for (int e = 0; e < NE; e++) acc[e] += xv * w[e];
    }
#pragma unroll
    for (int e = 0; e < NE; e++)
#pragma unroll
        for (int o = 16; o > 0; o >>= 1)
            acc[e] += __shfl_down_sync(0xffffffffu, acc[e], o);
    if (lane == 0) {
        float l[NE];
#pragma unroll
        for (int e = 0; e < NE; e++) l[e] = acc[e] + rb[e];
        float m = l[0];
#pragma unroll
        for (int e = 1; e < NE; e++) m = fmaxf(m, l[e]);
        float p[NE], s = 0.f;
#pragma unroll
        for (int e = 0; e < NE; e++) { p[e] = expf(l[e] - m); s += p[e]; }
        float inv = 1.f / s;
#pragma unroll
        for (int e = 0; e < NE; e++) p[e] *= inv;
        int i1 = 0; float p1 = p[0];
#pragma unroll
        for (int e = 1; e < NE; e++) if (p[e] > p1) { p1 = p[e]; i1 = e; }
        int i2 = -1; float p2 = -1.f;
#pragma unroll
        for (int e = 0; e < NE; e++) if (e != i1 && p[e] > p2) { p2 = p[e]; i2 = e; }
        float sum = fmaxf(p1 + p2, 1e-9f);
        g_topk_i[warp * 2 + 0] = i1;
        g_topk_i[warp * 2 + 1] = i2;
        g_topk_w[warp * 2 + 0] = p1 / sum;
        g_topk_w[warp * 2 + 1] = p2 / sum;
    }
}

// ---------------------------------------------------------------------------
// K4: stable rank / capacity / slot table (single block)
// ---------------------------------------------------------------------------
__global__ void rank_kernel() {
    __shared__ int cnts[256][NE];
    int tid = threadIdx.x;
    int base = tid * (NA / 256);
    int local[NE];
#pragma unroll
    for (int e = 0; e < NE; e++) local[e] = 0;
    for (int a = base; a < base + NA / 256; a++) local[g_topk_i[a]]++;
#pragma unroll
    for (int e = 0; e < NE; e++) cnts[tid][e] = local[e];
    __syncthreads();
    if (tid < NE) {
        int run = 0;
        for (int i = 0; i < 256; i++) { int t = cnts[i][tid]; cnts[i][tid] = run; run += t; }
        g_cnt[tid] = min(run, CAP);
    }
    __syncthreads();
#pragma unroll
    for (int e = 0; e < NE; e++) local[e] = cnts[tid][e];
    for (int a = base; a < base + NA / 256; a++) {
        int e = g_topk_i[a];
        int r = local[e]++;
        if (r < CAP) {
            g_slot_tok[e * CAP + r] = a >> 1;
            g_slot_w[e * CAP + r] = g_topk_w[a];
        }
    }
}

// ---------------------------------------------------------------------------
// GEMM compute: one 64-half K-chunk. 8 warps 4m x 2n; warp tile 64x64 =
// 4x8 m16n8k16. ldmatrix x4 fragments, XOR-swizzled smem (128B rows).
// ---------------------------------------------------------------------------
__device__ __forceinline__ void compute_stage(uint32_t sA, uint32_t sB,
                                              int warp_m, int warp_n, int lane,
                                              float acc[4][8][4]) {
    int cg_a = lane >> 4;                  // A col-group (0/1)
    int la15 = lane & 15;
    int cg_b = (lane >> 3) & 1;            // B col-group
    int n_off = ((lane >> 4) << 3) + (lane & 7);
#pragma unroll
    for (int k16 = 0; k16 < 4; k16++) {
        uint32_t af[4][4];
#pragma unroll
        for (int mt = 0; mt < 4; mt++) {
            int row = warp_m + mt * 16 + la15;
            uint32_t addr = sA + (uint32_t)(row << 7)
                          + (uint32_t)((((k16 << 1) + cg_a) ^ (row & 7)) << 4);
            LDSM4(af[mt][0], af[mt][1], af[mt][2], af[mt][3], addr);
        }
        uint32_t bf[8][2];
#pragma unroll
        for (int p = 0; p < 4; p++) {
            int rn = warp_n + p * 16 + n_off;
            uint32_t addr = sB + (uint32_t)(rn << 7)
                          + (uint32_t)((((k16 << 1) + cg_b) ^ (rn & 7)) << 4);
            LDSM4(bf[2 * p][0], bf[2 * p][1], bf[2 * p + 1][0], bf[2 * p + 1][1], addr);
        }
#pragma unroll
        for (int mt = 0; mt < 4; mt++)
#pragma unroll
            for (int nt = 0; nt < 8; nt++)
                mma16(acc[mt][nt], af[mt], bf[nt]);
    }
}

// K5: GEMM1 + bias + gelu -> g_Hh
__global__ __launch_bounds__(256, 1)
void gemm1_kernel(const float* __restrict__ b1) {
    int e = blockIdx.z;
    int cnt = g_cnt[e];
    int row0 = blockIdx.y * BM;
    if (row0 >= cnt) return;
    int col0 = blockIdx.x * BN;

    extern __shared__ __align__(128) char smem[];
    uint32_t sb = smem_u32(smem);

    int tid = threadIdx.x;
    int wid = tid >> 5, lane = tid & 31;
    int warp_m = (wid >> 1) * 64, warp_n = (wid & 1) * 64;
    int g = lane >> 2, t4 = lane & 3;

    // loader: thread covers rows (tid>>3)+32q, 16B chunk (tid&7)
    int c8 = tid & 7;
    int rb = tid >> 3;
    const __half* aP[8];
    const __half* bP[4];
    uint32_t stA[8], stB[4];
    const __half* w1e = g_w1h + (size_t)e * F_FF * D_MODEL;
#pragma unroll
    for (int q = 0; q < 8; q++) {
        int r = rb + 32 * q;
        int grow = row0 + r;
        int tok = (grow < cnt) ? g_slot_tok[e * CAP + grow] : 0;
        aP[q] = g_xh + (size_t)tok * D_MODEL + c8 * 8;
        stA[q] = sb + (uint32_t)((r << 7) + ((c8 ^ (r & 7)) << 4));
    }
#pragma unroll
    for (int q = 0; q < 4; q++) {
        int r = rb + 32 * q;
        bP[q] = w1e + (size_t)(col0 + r) * D_MODEL + c8 * 8;
        stB[q] = sb + ASTG + (uint32_t)((r << 7) + ((c8 ^ (r & 7)) << 4));
    }

    float acc[4][8][4];
#pragma unroll
    for (int mt = 0; mt < 4; mt++)
#pragma unroll
        for (int nt = 0; nt < 8; nt++)
#pragma unroll
            for (int k = 0; k < 4; k++) acc[mt][nt][k] = 0.f;

    const int NCH = D_MODEL / 64;   // 16

#pragma unroll
    for (int c = 0; c < 2; c++) {
        uint32_t so = (uint32_t)(c * STAGEB);
#pragma unroll
        for (int q = 0; q < 8; q++) { cp16(stA[q] + so, aP[q]); aP[q] += 64; }
#pragma unroll
        for (int q = 0; q < 4; q++) { cp16(stB[q] + so, bP[q]); bP[q] += 64; }
        asm volatile("cp.async.commit_group;" ::: "memory");
    }

    for (int i = 0; i < NCH; i++) {
        if (i + 2 < NCH) {
            uint32_t so = (uint32_t)(((i + 2) % NSTAGE) * STAGEB);
#pragma unroll
            for (int q = 0; q < 8; q++) { cp16(stA[q] + so, aP[q]); aP[q] += 64; }
#pragma unroll
            for (int q = 0; q < 4; q++) { cp16(stB[q] + so, bP[q]); bP[q] += 64; }
            asm volatile("cp.async.commit_group;" ::: "memory");
            asm volatile("cp.async.wait_group 2;" ::: "memory");
        } else if (i + 1 < NCH) {
            asm volatile("cp.async.wait_group 1;" ::: "memory");
        } else {
            asm volatile("cp.async.wait_group 0;" ::: "memory");
        }
        __syncthreads();
        uint32_t stg = sb + (uint32_t)((i % NSTAGE) * STAGEB);
        compute_stage(stg, stg + ASTG, warp_m, warp_n, lane, acc);
        __syncthreads();
    }

    // epilogue: bias + gelu -> H fp16
    const float* bp = b1 + e * F_FF + col0;
#pragma unroll
    for (int mt = 0; mt < 4; mt++) {
#pragma unroll
        for (int h = 0; h < 2; h++) {
            int r = row0 + warp_m + mt * 16 + g + h * 8;
            __half* Hrow = g_Hh + ((size_t)e * CAP + r) * F_FF + col0;
#pragma unroll
            for (int nt = 0; nt < 8; nt++) {
                int c = warp_n + nt * 8 + 2 * t4;
                float v0 = acc[mt][nt][2 * h + 0] + bp[c];
                float v1 = acc[mt][nt][2 * h + 1] + bp[c + 1];
                v0 = 0.5f * v0 * (1.f + erff(v0 * 0.70710678118654752f));
                v1 = 0.5f * v1 * (1.f + erff(v1 * 0.70710678118654752f));
                *(__half2*)(Hrow + c) = __floats2half2_rn(v0, v1);
            }
        }
    }
}

// K6: GEMM2 + bias + gated atomic scatter -> out
__global__ __launch_bounds__(256, 1)
void gemm2_kernel(const float* __restrict__ b2, float* __restrict__ out) {
    int e = blockIdx.z;
    int cnt = g_cnt[e];
    int row0 = blockIdx.y * BM;
    if (row0 >= cnt) return;
    int col0 = blockIdx.x * BN;

    extern __shared__ __align__(128) char smem[];
    uint32_t sb = smem_u32(smem);

    int tid = threadIdx.x;
    int wid = tid >> 5, lane = tid & 31;
    int warp_m = (wid >> 1) * 64, warp_n = (wid & 1) * 64;
    int g = lane >> 2, t4 = lane & 3;

    int c8 = tid & 7;
    int rb = tid >> 3;
    const __half* aP[8];
    const __half* bP[4];
    uint32_t stA[8], stB[4];
    const __half* w2e = g_w2h + (size_t)e * D_MODEL * F_FF;
    const __half* He = g_Hh + (size_t)e * CAP * F_FF;
#pragma unroll
    for (int q = 0; q < 8; q++) {
        int r = rb + 32 * q;
        aP[q] = He + (size_t)(row0 + r) * F_FF + c8 * 8;
        stA[q] = sb + (uint32_t)((r << 7) + ((c8 ^ (r & 7)) << 4));
    }
#pragma unroll
    for (int q = 0; q < 4; q++) {
        int r = rb + 32 * q;
        bP[q] = w2e + (size_t)(col0 + r) * F_FF + c8 * 8;
        stB[q] = sb + ASTG + (uint32_t)((r << 7) + ((c8 ^ (r & 7)) << 4));
    }

    float acc[4][8][4];
#pragma unroll
    for (int mt = 0; mt < 4; mt++)
#pragma unroll
        for (int nt = 0; nt < 8; nt++)
#pragma unroll
            for (int k = 0; k < 4; k++) acc[mt][nt][k] = 0.f;

    const int NCH = F_FF / 64;   // 32

#pragma unroll
    for (int c = 0; c < 2; c++) {
        uint32_t so = (uint32_t)(c * STAGEB);
#pragma unroll
        for (int q = 0; q < 8; q++) { cp16(stA[q] + so, aP[q]); aP[q] += 64; }
#pragma unroll
        for (int q = 0; q < 4; q++) { cp16(stB[q] + so, bP[q]); bP[q] += 64; }
        asm volatile("cp.async.commit_group;" ::: "memory");
    }

    for (int i = 0; i < NCH; i++) {
        if (i + 2 < NCH) {
            uint32_t so = (uint32_t)(((i + 2) % NSTAGE) * STAGEB);
#pragma unroll
            for (int q = 0; q < 8; q++) { cp16(stA[q] + so, aP[q]); aP[q] += 64; }
#pragma unroll
            for (int q = 0; q < 4; q++) { cp16(stB[q] + so, bP[q]); bP[q] += 64; }
            asm volatile("cp.async.commit_group;" ::: "memory");
            asm volatile("cp.async.wait_group 2;" ::: "memory");
        } else if (i + 1 < NCH) {
            asm volatile("cp.async.wait_group 1;" ::: "memory");
        } else {
            asm volatile("cp.async.wait_group 0;" ::: "memory");
        }
        __syncthreads();
        uint32_t stg = sb + (uint32_t)((i % NSTAGE) * STAGEB);
        compute_stage(stg, stg + ASTG, warp_m, warp_n, lane, acc);
        __syncthreads();
    }

    // epilogue: bias + gate + atomic scatter
    const float* bp = b2 + e * D_MODEL + col0;
#pragma unroll
    for (int mt = 0; mt < 4; mt++) {
#pragma unroll
        for (int h = 0; h < 2; h++) {
            int r = row0 + warp_m + mt * 16 + g + h * 8;
            if (r < cnt) {
                int   tok = g_slot_tok[e * CAP + r];
                float w   = g_slot_w[e * CAP + r];
                float* orow = out + (size_t)tok * D_MODEL + col0;
#pragma unroll
                for (int nt = 0; nt < 8; nt++) {
                    int c = warp_n + nt * 8 + 2 * t4;
                    atomicAdd(orow + c,     (acc[mt][nt][2 * h + 0] + bp[c])     * w);
                    atomicAdd(orow + c + 1, (acc[mt][nt][2 * h + 1] + bp[c + 1]) * w);
                }
            }
        }
    }
}

// ---------------------------------------------------------------------------
extern "C" void kernel_launch(void* const* d_in, const int* in_sizes, int n_in,
                              void* d_out, int out_size) {
    const float* x  = (const float*)d_in[0];
    const float* rw = (const float*)d_in[1];
    const float* rb = (const float*)d_in[2];
    const float* w1 = (const float*)d_in[3];
    const float* b1 = (const float*)d_in[4];
    const float* w2 = (const float*)d_in[5];
    const float* b2 = (const float*)d_in[6];
    float* out = (float*)d_out;

    cudaFuncSetAttribute(gemm1_kernel, cudaFuncAttributeMaxDynamicSharedMemorySize, DSMEM_BYTES);
    cudaFuncSetAttribute(gemm2_kernel, cudaFuncAttributeMaxDynamicSharedMemorySize, DSMEM_BYTES);

    int n4 = out_size / 4;
    zero_kernel<<<(n4 + 255) / 256, 256>>>((float4*)out, n4);

    {   // x -> fp16
        __half* xh;
        cudaGetSymbolAddress((void**)&xh, g_xh);
        int n2 = T_TOK * D_MODEL / 2;
        conv_x_kernel<<<(n2 + 255) / 256, 256>>>((const float2*)x, (__half2*)xh, n2);
    }
    {   // transpose + convert weights to fp16
        __half *w1h, *w2h;
        cudaGetSymbolAddress((void**)&w1h, g_w1h);
        cudaGetSymbolAddress((void**)&w2h, g_w2h);
        dim3 b(32, 8);
        dim3 g1(F_FF / 32, D_MODEL / 32, NE);   // w1: R=D, C=F
        transpose_kernel<<<g1, b>>>(w1, w1h, D_MODEL, F_FF);
        dim3 g2(D_MODEL / 32, F_FF / 32, NE);   // w2: R=F, C=D
        transpose_kernel<<<g2, b>>>(w2, w2h, F_FF, D_MODEL);
    }

    router_kernel<<<T_TOK / 8, 256>>>(x, rw, rb);
    rank_kernel<<<1, 256>>>();

    dim3 gg1(F_FF / BN, CAP / BM, NE);
    gemm1_kernel<<<gg1, 256, DSMEM_BYTES>>>(b1);
    dim3 gg2(D_MODEL / BN, CAP / BM, NE);
    gemm2_kernel<<<gg2, 256, DSMEM_BYTES>>>(b2, out);
}

// round 6
// speedup vs baseline: 4.7645x; 1.0089x over previous
#include <cuda_runtime.h>
#include <cuda_fp16.h>
#include <cstdint>
#include <math.h>

// ---------------------------------------------------------------------------
// Problem constants
// ---------------------------------------------------------------------------
#define T_TOK   8192
#define D_MODEL 1024
#define F_FF    2048
#define NE      8
#define CAP     2560
#define NA      (T_TOK * 2)

#define BM      256
#define BN      128
#define NRB     (CAP / BM)               // 10 row blocks per expert
#define G1B     (NE * NRB * (F_FF / BN)) // 1280 gemm1 tiles
#define G2B     (NE * NRB * (D_MODEL / BN)) // 640 gemm2 tiles

// ---------------------------------------------------------------------------
// Device scratch
// ---------------------------------------------------------------------------
__device__ __half g_xh [(size_t)T_TOK * D_MODEL];       // fp16 x
__device__ __half g_w1h[(size_t)NE * F_FF * D_MODEL];   // w1^T [e][f][k] fp16
__device__ __half g_w2h[(size_t)NE * D_MODEL * F_FF];   // w2^T [e][d][f] fp16
__device__ __half g_Hh [(size_t)NE * CAP * F_FF];       // gelu output fp16
__device__ int    g_topk_i[NA];
__device__ float  g_topk_w[NA];
__device__ int    g_slot_tok[NE * CAP];
__device__ float  g_slot_w[NE * CAP];
__device__ int    g_cnt[NE];
__device__ int    g_ready[NE * NRB];                    // gemm1 col-tile completion counters

// ---------------------------------------------------------------------------
// Helpers
// ---------------------------------------------------------------------------
__device__ __forceinline__ uint32_t smem_u32(const void* p) {
    uint32_t a;
    asm("{ .reg .u64 t; cvta.to.shared.u64 t, %1; cvt.u32.u64 %0, t; }" : "=r"(a) : "l"(p));
    return a;
}
__device__ __forceinline__ void cp16(uint32_t dst, const void* src) {
    asm volatile("cp.async.cg.shared.global [%0], [%1], 16;" :: "r"(dst), "l"(src));
}
__device__ __forceinline__ void mma16(float* d, const uint32_t* a, const uint32_t* b) {
    asm volatile(
        "mma.sync.aligned.m16n8k16.row.col.f32.f16.f16.f32 "
        "{%0,%1,%2,%3}, {%4,%5,%6,%7}, {%8,%9}, {%0,%1,%2,%3};"
        : "+f"(d[0]), "+f"(d[1]), "+f"(d[2]), "+f"(d[3])
        : "r"(a[0]), "r"(a[1]), "r"(a[2]), "r"(a[3]), "r"(b[0]), "r"(b[1]));
}
#define LDSM4(r0, r1, r2, r3, a) \
    asm volatile("ldmatrix.sync.aligned.m8n8.x4.shared.b16 {%0,%1,%2,%3}, [%4];" \
                 : "=r"(r0), "=r"(r1), "=r"(r2), "=r"(r3) : "r"(a))

#define ASTG    32768                    // A bytes per stage (256 rows * 128B)
#define BSTG    16384                    // B bytes per stage (128 rows * 128B)
#define STAGEB  (ASTG + BSTG)            // 48 KB
#define NSTAGE  3
#define DSMEM_BYTES (NSTAGE * STAGEB)    // 144 KB

// ---------------------------------------------------------------------------
// K0: zero output
// ---------------------------------------------------------------------------
__global__ void zero_kernel(float4* __restrict__ out, int n4) {
    int i = blockIdx.x * blockDim.x + threadIdx.x;
    if (i < n4) out[i] = make_float4(0.f, 0.f, 0.f, 0.f);
}

// ---------------------------------------------------------------------------
// K1: transpose+convert weights: src [e][R][C] fp32 -> dst [e][C][R] fp16
// ---------------------------------------------------------------------------
__global__ void transpose_kernel(const float* __restrict__ src, __half* __restrict__ dst,
                                 int R, int C) {
    __shared__ float t[32][33];
    int e = blockIdx.z;
    const float* s = src + (size_t)e * R * C;
    __half* d = dst + (size_t)e * R * C;
    int c0 = blockIdx.x * 32, r0 = blockIdx.y * 32;
    int tx = threadIdx.x, ty = threadIdx.y;   // (32, 8)
#pragma unroll
    for (int j = 0; j < 32; j += 8)
        t[ty + j][tx] = s[(size_t)(r0 + ty + j) * C + c0 + tx];
    __syncthreads();
#pragma unroll
    for (int j = 0; j < 32; j += 8)
        d[(size_t)(c0 + ty + j) * R + r0 + tx] = __float2half_rn(t[tx][ty + j]);
}

// ---------------------------------------------------------------------------
// K2: router + x->fp16 (one pass over x; one warp per token)
// ---------------------------------------------------------------------------
__global__ void router_kernel(const float* __restrict__ x,
                              const float* __restrict__ rw,
                              const float* __restrict__ rb) {
    int warp = (blockIdx.x * blockDim.x + threadIdx.x) >> 5;
    int lane = threadIdx.x & 31;
    if (warp >= T_TOK) return;
    const float* xr = x + (size_t)warp * D_MODEL;
    __half* xo = g_xh + (size_t)warp * D_MODEL;
    float acc[NE];
#pragma unroll
    for (int e = 0; e < NE; e++) acc[e] = 0.f;
    for (int d = lane; d < D_MODEL; d += 32) {
        float xv = xr[d];
        xo[d] = __float2half_rn(xv);
        const float* w = rw + d * NE;
#pragma unroll
        for (int e = 0; e < NE; e++) acc[e] += xv * w[e];
    }
#pragma unroll
    for (int e = 0; e < NE; e++)
#pragma unroll
        for (int o = 16; o > 0; o >>= 1)
            acc[e] += __shfl_down_sync(0xffffffffu, acc[e], o);
    if (lane == 0) {
        float l[NE];
#pragma unroll
        for (int e = 0; e < NE; e++) l[e] = acc[e] + rb[e];
        float m = l[0];
#pragma unroll
        for (int e = 1; e < NE; e++) m = fmaxf(m, l[e]);
        float p[NE], s = 0.f;
#pragma unroll
        for (int e = 0; e < NE; e++) { p[e] = expf(l[e] - m); s += p[e]; }
        float inv = 1.f / s;
#pragma unroll
        for (int e = 0; e < NE; e++) p[e] *= inv;
        int i1 = 0; float p1 = p[0];
#pragma unroll
        for (int e = 1; e < NE; e++) if (p[e] > p1) { p1 = p[e]; i1 = e; }
        int i2 = -1; float p2 = -1.f;
#pragma unroll
        for (int e = 0; e < NE; e++) if (e != i1 && p[e] > p2) { p2 = p[e]; i2 = e; }
        float sum = fmaxf(p1 + p2, 1e-9f);
        g_topk_i[warp * 2 + 0] = i1;
        g_topk_i[warp * 2 + 1] = i2;
        g_topk_w[warp * 2 + 0] = p1 / sum;
        g_topk_w[warp * 2 + 1] = p2 / sum;
    }
}

// ---------------------------------------------------------------------------
// K3: stable rank / capacity / slot table / zero readiness (single block)
// ---------------------------------------------------------------------------
__global__ void rank_kernel() {
    __shared__ int cnts[256][NE];
    int tid = threadIdx.x;
    if (tid < NE * NRB) g_ready[tid] = 0;
    int base = tid * (NA / 256);
    int local[NE];
#pragma unroll
    for (int e = 0; e < NE; e++) local[e] = 0;
    for (int a = base; a < base + NA / 256; a++) local[g_topk_i[a]]++;
#pragma unroll
    for (int e = 0; e < NE; e++) cnts[tid][e] = local[e];
    __syncthreads();
    if (tid < NE) {
        int run = 0;
        for (int i = 0; i < 256; i++) { int t = cnts[i][tid]; cnts[i][tid] = run; run += t; }
        g_cnt[tid] = min(run, CAP);
    }
    __syncthreads();
#pragma unroll
    for (int e = 0; e < NE; e++) local[e] = cnts[tid][e];
    for (int a = base; a < base + NA / 256; a++) {
        int e = g_topk_i[a];
        int r = local[e]++;
        if (r < CAP) {
            g_slot_tok[e * CAP + r] = a >> 1;
            g_slot_w[e * CAP + r] = g_topk_w[a];
        }
    }
}

// ---------------------------------------------------------------------------
// GEMM compute: one 64-half K-chunk. 8 warps 4m x 2n; warp tile 64x64 =
// 4x8 m16n8k16. ldmatrix x4 fragments, XOR-swizzled smem (128B rows).
// ---------------------------------------------------------------------------
__device__ __forceinline__ void compute_stage(uint32_t sA, uint32_t sB,
                                              int warp_m, int warp_n, int lane,
                                              float acc[4][8][4]) {
    int cg_a = lane >> 4;                  // A col-group (0/1)
    int la15 = lane & 15;
    int cg_b = (lane >> 3) & 1;            // B col-group
    int n_off = ((lane >> 4) << 3) + (lane & 7);
#pragma unroll
    for (int k16 = 0; k16 < 4; k16++) {
        uint32_t af[4][4];
#pragma unroll
        for (int mt = 0; mt < 4; mt++) {
            int row = warp_m + mt * 16 + la15;
            uint32_t addr = sA + (uint32_t)(row << 7)
                          + (uint32_t)((((k16 << 1) + cg_a) ^ (row & 7)) << 4);
            LDSM4(af[mt][0], af[mt][1], af[mt][2], af[mt][3], addr);
        }
        uint32_t bf[8][2];
#pragma unroll
        for (int p = 0; p < 4; p++) {
            int rn = warp_n + p * 16 + n_off;
            uint32_t addr = sB + (uint32_t)(rn << 7)
                          + (uint32_t)((((k16 << 1) + cg_b) ^ (rn & 7)) << 4);
            LDSM4(bf[2 * p][0], bf[2 * p][1], bf[2 * p + 1][0], bf[2 * p + 1][1], addr);
        }
#pragma unroll
        for (int mt = 0; mt < 4; mt++)
#pragma unroll
            for (int nt = 0; nt < 8; nt++)
                mma16(acc[mt][nt], af[mt], bf[nt]);
    }
}

// ---------------------------------------------------------------------------
// K4: fused GEMM1 + GEMM2, single launch.
// blocks [0, G1B): gemm1 tiles;  [G1B, G1B+G2B): gemm2 tiles (spin on deps).
// ---------------------------------------------------------------------------
__global__ __launch_bounds__(256, 1)
void fused_gemm_kernel(const float* __restrict__ b1,
                       const float* __restrict__ b2,
                       float* __restrict__ out) {
    extern __shared__ __align__(128) char smem[];
    uint32_t sb = smem_u32(smem);
    int tid = threadIdx.x;
    int wid = tid >> 5, lane = tid & 31;
    int warp_m = (wid >> 1) * 64, warp_n = (wid & 1) * 64;
    int g = lane >> 2, t4 = lane & 3;
    int c8 = tid & 7;
    int rbt = tid >> 3;

    int bid = blockIdx.x;

    if (bid < G1B) {
        // ---------------- GEMM1 tile ----------------
        int cb = bid & 15;                 // 16 col tiles
        int erb = bid >> 4;                // e * NRB + rowblk
        int e = erb / NRB;
        int row0 = (erb % NRB) * BM;
        int cnt = g_cnt[e];
        if (row0 >= cnt) return;
        int col0 = cb * BN;

        const __half* aP[8];
        const __half* bP[4];
        uint32_t stA[8], stB[4];
        const __half* w1e = g_w1h + (size_t)e * F_FF * D_MODEL;
#pragma unroll
        for (int q = 0; q < 8; q++) {
            int r = rbt + 32 * q;
            int grow = row0 + r;
            int tok = (grow < cnt) ? g_slot_tok[e * CAP + grow] : 0;
            aP[q] = g_xh + (size_t)tok * D_MODEL + c8 * 8;
            stA[q] = sb + (uint32_t)((r << 7) + ((c8 ^ (r & 7)) << 4));
        }
#pragma unroll
        for (int q = 0; q < 4; q++) {
            int r = rbt + 32 * q;
            bP[q] = w1e + (size_t)(col0 + r) * D_MODEL + c8 * 8;
            stB[q] = sb + ASTG + (uint32_t)((r << 7) + ((c8 ^ (r & 7)) << 4));
        }

        float acc[4][8][4];
#pragma unroll
        for (int mt = 0; mt < 4; mt++)
#pragma unroll
            for (int nt = 0; nt < 8; nt++)
#pragma unroll
                for (int k = 0; k < 4; k++) acc[mt][nt][k] = 0.f;

        const int NCH = D_MODEL / 64;   // 16
#pragma unroll
        for (int c = 0; c < 2; c++) {
            uint32_t so = (uint32_t)(c * STAGEB);
#pragma unroll
            for (int q = 0; q < 8; q++) { cp16(stA[q] + so, aP[q]); aP[q] += 64; }
#pragma unroll
            for (int q = 0; q < 4; q++) { cp16(stB[q] + so, bP[q]); bP[q] += 64; }
            asm volatile("cp.async.commit_group;" ::: "memory");
        }
        for (int i = 0; i < NCH; i++) {
            if (i + 2 < NCH) {
                uint32_t so = (uint32_t)(((i + 2) % NSTAGE) * STAGEB);
#pragma unroll
                for (int q = 0; q < 8; q++) { cp16(stA[q] + so, aP[q]); aP[q] += 64; }
#pragma unroll
                for (int q = 0; q < 4; q++) { cp16(stB[q] + so, bP[q]); bP[q] += 64; }
                asm volatile("cp.async.commit_group;" ::: "memory");
                asm volatile("cp.async.wait_group 2;" ::: "memory");
            } else if (i + 1 < NCH) {
                asm volatile("cp.async.wait_group 1;" ::: "memory");
            } else {
                asm volatile("cp.async.wait_group 0;" ::: "memory");
            }
            __syncthreads();
            uint32_t stg = sb + (uint32_t)((i % NSTAGE) * STAGEB);
            compute_stage(stg, stg + ASTG, warp_m, warp_n, lane, acc);
            __syncthreads();
        }

        // epilogue: bias + gelu -> H fp16
        const float* bp = b1 + e * F_FF + col0;
#pragma unroll
        for (int mt = 0; mt < 4; mt++) {
#pragma unroll
            for (int h = 0; h < 2; h++) {
                int r = row0 + warp_m + mt * 16 + g + h * 8;
                __half* Hrow = g_Hh + ((size_t)e * CAP + r) * F_FF + col0;
#pragma unroll
                for (int nt = 0; nt < 8; nt++) {
                    int c = warp_n + nt * 8 + 2 * t4;
                    float v0 = acc[mt][nt][2 * h + 0] + bp[c];
                    float v1 = acc[mt][nt][2 * h + 1] + bp[c + 1];
                    v0 = 0.5f * v0 * (1.f + erff(v0 * 0.70710678118654752f));
                    v1 = 0.5f * v1 * (1.f + erff(v1 * 0.70710678118654752f));
                    *(__half2*)(Hrow + c) = __floats2half2_rn(v0, v1);
                }
            }
        }
        // publish completion
        __syncthreads();
        if (tid == 0) {
            __threadfence();
            atomicAdd(&g_ready[erb], 1);
        }
    } else {
        // ---------------- GEMM2 tile ----------------
        int b2id = bid - G1B;
        int cb = b2id & 7;                 // 8 col tiles
        int erb = b2id >> 3;
        int e = erb / NRB;
        int row0 = (erb % NRB) * BM;
        int cnt = g_cnt[e];
        if (row0 >= cnt) return;
        int col0 = cb * BN;

        // wait for all 16 gemm1 col-tiles of (e, rowblk)
        if (tid == 0) {
            while (atomicAdd(&g_ready[erb], 0) < 16) __nanosleep(200);
        }
        __syncthreads();
        __threadfence();

        const __half* aP[8];
        const __half* bP[4];
        uint32_t stA[8], stB[4];
        const __half* w2e = g_w2h + (size_t)e * D_MODEL * F_FF;
        const __half* He = g_Hh + (size_t)e * CAP * F_FF;
#pragma unroll
        for (int q = 0; q < 8; q++) {
            int r = rbt + 32 * q;
            aP[q] = He + (size_t)(row0 + r) * F_FF + c8 * 8;
            stA[q] = sb + (uint32_t)((r << 7) + ((c8 ^ (r & 7)) << 4));
        }
#pragma unroll
        for (int q = 0; q < 4; q++) {
            int r = rbt + 32 * q;
            bP[q] = w2e + (size_t)(col0 + r) * F_FF + c8 * 8;
            stB[q] = sb + ASTG + (uint32_t)((r << 7) + ((c8 ^ (r & 7)) << 4));
        }

        float acc[4][8][4];
#pragma unroll
        for (int mt = 0; mt < 4; mt++)
#pragma unroll
            for (int nt = 0; nt < 8; nt++)
#pragma unroll
                for (int k = 0; k < 4; k++) acc[mt][nt][k] = 0.f;

        const int NCH = F_FF / 64;   // 32
#pragma unroll
        for (int c = 0; c < 2; c++) {
            uint32_t so = (uint32_t)(c * STAGEB);
#pragma unroll
            for (int q = 0; q < 8; q++) { cp16(stA[q] + so, aP[q]); aP[q] += 64; }
#pragma unroll
            for (int q = 0; q < 4; q++) { cp16(stB[q] + so, bP[q]); bP[q] += 64; }
            asm volatile("cp.async.commit_group;" ::: "memory");
        }
        for (int i = 0; i < NCH; i++) {
            if (i + 2 < NCH) {
                uint32_t so = (uint32_t)(((i + 2) % NSTAGE) * STAGEB);
#pragma unroll
                for (int q = 0; q < 8; q++) { cp16(stA[q] + so, aP[q]); aP[q] += 64; }
#pragma unroll
                for (int q = 0; q < 4; q++) { cp16(stB[q] + so, bP[q]); bP[q] += 64; }
                asm volatile("cp.async.commit_group;" ::: "memory");
                asm volatile("cp.async.wait_group 2;" ::: "memory");
            } else if (i + 1 < NCH) {
                asm volatile("cp.async.wait_group 1;" ::: "memory");
            } else {
                asm volatile("cp.async.wait_group 0;" ::: "memory");
            }
            __syncthreads();
            uint32_t stg = sb + (uint32_t)((i % NSTAGE) * STAGEB);
            compute_stage(stg, stg + ASTG, warp_m, warp_n, lane, acc);
            __syncthreads();
        }

        // epilogue: bias + gate + atomic scatter
        const float* bp = b2 + e * D_MODEL + col0;
#pragma unroll
        for (int mt = 0; mt < 4; mt++) {
#pragma unroll
            for (int h = 0; h < 2; h++) {
                int r = row0 + warp_m + mt * 16 + g + h * 8;
                if (r < cnt) {
                    int   tok = g_slot_tok[e * CAP + r];
                    float w   = g_slot_w[e * CAP + r];
                    float* orow = out + (size_t)tok * D_MODEL + col0;
#pragma unroll
                    for (int nt = 0; nt < 8; nt++) {
                        int c = warp_n + nt * 8 + 2 * t4;
                        atomicAdd(orow + c,     (acc[mt][nt][2 * h + 0] + bp[c])     * w);
                        atomicAdd(orow + c + 1, (acc[mt][nt][2 * h + 1] + bp[c + 1]) * w);
                    }
                }
            }
        }
    }
}

// ---------------------------------------------------------------------------
extern "C" void kernel_launch(void* const* d_in, const int* in_sizes, int n_in,
                              void* d_out, int out_size) {
    const float* x  = (const float*)d_in[0];
    const float* rw = (const float*)d_in[1];
    const float* rb = (const float*)d_in[2];
    const float* w1 = (const float*)d_in[3];
    const float* b1 = (const float*)d_in[4];
    const float* w2 = (const float*)d_in[5];
    const float* b2 = (const float*)d_in[6];
    float* out = (float*)d_out;

    cudaFuncSetAttribute(fused_gemm_kernel, cudaFuncAttributeMaxDynamicSharedMemorySize, DSMEM_BYTES);

    int n4 = out_size / 4;
    zero_kernel<<<(n4 + 255) / 256, 256>>>((float4*)out, n4);

    router_kernel<<<T_TOK / 8, 256>>>(x, rw, rb);
    rank_kernel<<<1, 256>>>();

    {   // transpose + convert weights to fp16
        __half *w1h, *w2h;
        cudaGetSymbolAddress((void**)&w1h, g_w1h);
        cudaGetSymbolAddress((void**)&w2h, g_w2h);
        dim3 b(32, 8);
        dim3 g1(F_FF / 32, D_MODEL / 32, NE);   // w1: R=D, C=F
        transpose_kernel<<<g1, b>>>(w1, w1h, D_MODEL, F_FF);
        dim3 g2(D_MODEL / 32, F_FF / 32, NE);   // w2: R=F, C=D
        transpose_kernel<<<g2, b>>>(w2, w2h, F_FF, D_MODEL);
    }

    fused_gemm_kernel<<<G1B + G2B, 256, DSMEM_BYTES>>>(b1, b2, out);
}

// round 7
// speedup vs baseline: 5.8008x; 1.2175x over previous
#include <cuda_runtime.h>
#include <cuda_fp16.h>
#include <cstdint>
#include <math.h>

// ---------------------------------------------------------------------------
// Problem constants
// ---------------------------------------------------------------------------
#define T_TOK   8192
#define D_MODEL 1024
#define F_FF    2048
#define NE      8
#define CAP     2560
#define NA      (T_TOK * 2)

#define BM      128
#define BN      128
#define NRB     (CAP / BM)                  // 20 row blocks per expert
#define G1B     (NE * NRB * (F_FF / BN))    // 2560 gemm1 tiles
#define G2B     (NE * NRB * (D_MODEL / BN)) // 1280 gemm2 tiles

// ---------------------------------------------------------------------------
// Device scratch
// ---------------------------------------------------------------------------
__device__ __half g_xh [(size_t)T_TOK * D_MODEL];       // fp16 x
__device__ __half g_w1h[(size_t)NE * F_FF * D_MODEL];   // w1^T [e][f][k] fp16
__device__ __half g_w2h[(size_t)NE * D_MODEL * F_FF];   // w2^T [e][d][f] fp16
__device__ __half g_Hh [(size_t)NE * CAP * F_FF];       // gelu output fp16
__device__ int    g_topk_i[NA];
__device__ float  g_topk_w[NA];
__device__ int    g_slot_tok[NE * CAP];
__device__ float  g_slot_w[NE * CAP];
__device__ int    g_cnt[NE];
__device__ int    g_ready[NE * NRB];                    // gemm1 col-tile completion counters

// ---------------------------------------------------------------------------
// Helpers
// ---------------------------------------------------------------------------
__device__ __forceinline__ uint32_t smem_u32(const void* p) {
    uint32_t a;
    asm("{ .reg .u64 t; cvta.to.shared.u64 t, %1; cvt.u32.u64 %0, t; }" : "=r"(a) : "l"(p));
    return a;
}
__device__ __forceinline__ void cp16(uint32_t dst, const void* src) {
    asm volatile("cp.async.cg.shared.global [%0], [%1], 16;" :: "r"(dst), "l"(src));
}
__device__ __forceinline__ void mma16(float* d, const uint32_t* a, const uint32_t* b) {
    asm volatile(
        "mma.sync.aligned.m16n8k16.row.col.f32.f16.f16.f32 "
        "{%0,%1,%2,%3}, {%4,%5,%6,%7}, {%8,%9}, {%0,%1,%2,%3};"
        : "+f"(d[0]), "+f"(d[1]), "+f"(d[2]), "+f"(d[3])
        : "r"(a[0]), "r"(a[1]), "r"(a[2]), "r"(a[3]), "r"(b[0]), "r"(b[1]));
}
__device__ __forceinline__ void red2(float* p, float v0, float v1) {
    asm volatile("red.global.add.v2.f32 [%0], {%1, %2};" :: "l"(p), "f"(v0), "f"(v1) : "memory");
}
#define LDSM4(r0, r1, r2, r3, a) \
    asm volatile("ldmatrix.sync.aligned.m8n8.x4.shared.b16 {%0,%1,%2,%3}, [%4];" \
                 : "=r"(r0), "=r"(r1), "=r"(r2), "=r"(r3) : "r"(a))

#define ASTG    16384                    // A bytes per stage (128 rows * 128B)
#define BSTG    16384                    // B bytes per stage
#define STAGEB  (ASTG + BSTG)            // 32 KB
#define NSTAGE  3
#define DSMEM_BYTES (NSTAGE * STAGEB)    // 96 KB -> 2 CTAs/SM

// ---------------------------------------------------------------------------
// K0: zero output
// ---------------------------------------------------------------------------
__global__ void zero_kernel(float4* __restrict__ out, int n4) {
    int i = blockIdx.x * blockDim.x + threadIdx.x;
    if (i < n4) out[i] = make_float4(0.f, 0.f, 0.f, 0.f);
}

// ---------------------------------------------------------------------------
// K1: transpose+convert weights: src [e][R][C] fp32 -> dst [e][C][R] fp16
// ---------------------------------------------------------------------------
__global__ void transpose_kernel(const float* __restrict__ src, __half* __restrict__ dst,
                                 int R, int C) {
    __shared__ float t[32][33];
    int e = blockIdx.z;
    const float* s = src + (size_t)e * R * C;
    __half* d = dst + (size_t)e * R * C;
    int c0 = blockIdx.x * 32, r0 = blockIdx.y * 32;
    int tx = threadIdx.x, ty = threadIdx.y;   // (32, 8)
#pragma unroll
    for (int j = 0; j < 32; j += 8)
        t[ty + j][tx] = s[(size_t)(r0 + ty + j) * C + c0 + tx];
    __syncthreads();
#pragma unroll
    for (int j = 0; j < 32; j += 8)
        d[(size_t)(c0 + ty + j) * R + r0 + tx] = __float2half_rn(t[tx][ty + j]);
}

// ---------------------------------------------------------------------------
// K2: router + x->fp16 (one pass over x; one warp per token)
// ---------------------------------------------------------------------------
__global__ void router_kernel(const float* __restrict__ x,
                              const float* __restrict__ rw,
                              const float* __restrict__ rb) {
    int warp = (blockIdx.x * blockDim.x + threadIdx.x) >> 5;
    int lane = threadIdx.x & 31;
    if (warp >= T_TOK) return;
    const float* xr = x + (size_t)warp * D_MODEL;
    __half* xo = g_xh + (size_t)warp * D_MODEL;
    float acc[NE];
#pragma unroll
    for (int e = 0; e < NE; e++) acc[e] = 0.f;
    for (int d = lane; d < D_MODEL; d += 32) {
        float xv = xr[d];
        xo[d] = __float2half_rn(xv);
        const float* w = rw + d * NE;
#pragma unroll
        for (int e = 0; e < NE; e++) acc[e] += xv * w[e];
    }
#pragma unroll
    for (int e = 0; e < NE; e++)
#pragma unroll
        for (int o = 16; o > 0; o >>= 1)
            acc[e] += __shfl_down_sync(0xffffffffu, acc[e], o);
    if (lane == 0) {
        float l[NE];
#pragma unroll
        for (int e = 0; e < NE; e++) l[e] = acc[e] + rb[e];
        float m = l[0];
#pragma unroll
        for (int e = 1; e < NE; e++) m = fmaxf(m, l[e]);
        float p[NE], s = 0.f;
#pragma unroll
        for (int e = 0; e < NE; e++) { p[e] = expf(l[e] - m); s += p[e]; }
        float inv = 1.f / s;
#pragma unroll
        for (int e = 0; e < NE; e++) p[e] *= inv;
        int i1 = 0; float p1 = p[0];
#pragma unroll
        for (int e = 1; e < NE; e++) if (p[e] > p1) { p1 = p[e]; i1 = e; }
        int i2 = -1; float p2 = -1.f;
#pragma unroll
        for (int e = 0; e < NE; e++) if (e != i1 && p[e] > p2) { p2 = p[e]; i2 = e; }
        float sum = fmaxf(p1 + p2, 1e-9f);
        g_topk_i[warp * 2 + 0] = i1;
        g_topk_i[warp * 2 + 1] = i2;
        g_topk_w[warp * 2 + 0] = p1 / sum;
        g_topk_w[warp * 2 + 1] = p2 / sum;
    }
}

// ---------------------------------------------------------------------------
// K3: stable rank / capacity / slot table / zero readiness (single block)
// ---------------------------------------------------------------------------
__global__ void rank_kernel() {
    __shared__ int cnts[256][NE];
    int tid = threadIdx.x;
    if (tid < NE * NRB) g_ready[tid] = 0;
    int base = tid * (NA / 256);
    int local[NE];
#pragma unroll
    for (int e = 0; e < NE; e++) local[e] = 0;
    for (int a = base; a < base + NA / 256; a++) local[g_topk_i[a]]++;
#pragma unroll
    for (int e = 0; e < NE; e++) cnts[tid][e] = local[e];
    __syncthreads();
    if (tid < NE) {
        int run = 0;
        for (int i = 0; i < 256; i++) { int t = cnts[i][tid]; cnts[i][tid] = run; run += t; }
        g_cnt[tid] = min(run, CAP);
    }
    __syncthreads();
#pragma unroll
    for (int e = 0; e < NE; e++) local[e] = cnts[tid][e];
    for (int a = base; a < base + NA / 256; a++) {
        int e = g_topk_i[a];
        int r = local[e]++;
        if (r < CAP) {
            g_slot_tok[e * CAP + r] = a >> 1;
            g_slot_w[e * CAP + r] = g_topk_w[a];
        }
    }
}

// ---------------------------------------------------------------------------
// GEMM compute: one 64-half K-chunk. 8 warps 2m x 4n; warp tile 64x32 =
// 4x4 m16n8k16. ldmatrix x4 fragments, XOR-swizzled smem (128B rows).
// ---------------------------------------------------------------------------
__device__ __forceinline__ void compute_stage(uint32_t sA, uint32_t sB,
                                              int warp_m, int warp_n, int lane,
                                              float acc[4][4][4]) {
    int cg_a = lane >> 4;                  // A col-group (0/1)
    int la15 = lane & 15;
    int cg_b = (lane >> 3) & 1;            // B col-group
    int n_off = ((lane >> 4) << 3) + (lane & 7);
#pragma unroll
    for (int k16 = 0; k16 < 4; k16++) {
        uint32_t af[4][4];
#pragma unroll
        for (int mt = 0; mt < 4; mt++) {
            int row = warp_m + mt * 16 + la15;
            uint32_t addr = sA + (uint32_t)(row << 7)
                          + (uint32_t)((((k16 << 1) + cg_a) ^ (row & 7)) << 4);
            LDSM4(af[mt][0], af[mt][1], af[mt][2], af[mt][3], addr);
        }
        uint32_t bf[4][2];
#pragma unroll
        for (int p = 0; p < 2; p++) {
            int rn = warp_n + p * 16 + n_off;
            uint32_t addr = sB + (uint32_t)(rn << 7)
                          + (uint32_t)((((k16 << 1) + cg_b) ^ (rn & 7)) << 4);
            LDSM4(bf[2 * p][0], bf[2 * p][1], bf[2 * p + 1][0], bf[2 * p + 1][1], addr);
        }
#pragma unroll
        for (int mt = 0; mt < 4; mt++)
#pragma unroll
            for (int nt = 0; nt < 4; nt++)
                mma16(acc[mt][nt], af[mt], bf[nt]);
    }
}

// ---------------------------------------------------------------------------
// K4: fused GEMM1 + GEMM2, single launch, 2 CTAs/SM.
// blocks [0, G1B): gemm1 tiles;  [G1B, G1B+G2B): gemm2 tiles (spin on deps).
// ---------------------------------------------------------------------------
__global__ __launch_bounds__(256, 2)
void fused_gemm_kernel(const float* __restrict__ b1,
                       const float* __restrict__ b2,
                       float* __restrict__ out) {
    extern __shared__ __align__(128) char smem[];
    uint32_t sb = smem_u32(smem);
    int tid = threadIdx.x;
    int wid = tid >> 5, lane = tid & 31;
    int warp_m = (wid >> 2) * 64, warp_n = (wid & 3) * 32;
    int g = lane >> 2, t4 = lane & 3;
    int c8 = tid & 7;
    int rbt = tid >> 3;

    int bid = blockIdx.x;

    if (bid < G1B) {
        // ---------------- GEMM1 tile ----------------
        int cb = bid & 15;                 // 16 col tiles
        int erb = bid >> 4;                // e * NRB + rowblk
        int e = erb / NRB;
        int row0 = (erb % NRB) * BM;
        int cnt = g_cnt[e];
        if (row0 >= cnt) return;
        int col0 = cb * BN;

        const __half* aP[4];
        const __half* bP[4];
        uint32_t stA[4], stB[4];
        const __half* w1e = g_w1h + (size_t)e * F_FF * D_MODEL;
#pragma unroll
        for (int q = 0; q < 4; q++) {
            int r = rbt + 32 * q;
            int grow = row0 + r;
            int tok = (grow < cnt) ? g_slot_tok[e * CAP + grow] : 0;
            aP[q] = g_xh + (size_t)tok * D_MODEL + c8 * 8;
            stA[q] = sb + (uint32_t)((r << 7) + ((c8 ^ (r & 7)) << 4));
            bP[q] = w1e + (size_t)(col0 + r) * D_MODEL + c8 * 8;
            stB[q] = sb + ASTG + stA[q] - sb;
        }

        float acc[4][4][4];
#pragma unroll
        for (int mt = 0; mt < 4; mt++)
#pragma unroll
            for (int nt = 0; nt < 4; nt++)
#pragma unroll
                for (int k = 0; k < 4; k++) acc[mt][nt][k] = 0.f;

        const int NCH = D_MODEL / 64;   // 16
#pragma unroll
        for (int c = 0; c < 2; c++) {
            uint32_t so = (uint32_t)(c * STAGEB);
#pragma unroll
            for (int q = 0; q < 4; q++) {
                cp16(stA[q] + so, aP[q]); aP[q] += 64;
                cp16(stB[q] + so, bP[q]); bP[q] += 64;
            }
            asm volatile("cp.async.commit_group;" ::: "memory");
        }
        for (int i = 0; i < NCH; i++) {
            if (i + 2 < NCH) {
                uint32_t so = (uint32_t)(((i + 2) % NSTAGE) * STAGEB);
#pragma unroll
                for (int q = 0; q < 4; q++) {
                    cp16(stA[q] + so, aP[q]); aP[q] += 64;
                    cp16(stB[q] + so, bP[q]); bP[q] += 64;
                }
                asm volatile("cp.async.commit_group;" ::: "memory");
                asm volatile("cp.async.wait_group 2;" ::: "memory");
            } else if (i + 1 < NCH) {
                asm volatile("cp.async.wait_group 1;" ::: "memory");
            } else {
                asm volatile("cp.async.wait_group 0;" ::: "memory");
            }
            __syncthreads();
            uint32_t stg = sb + (uint32_t)((i % NSTAGE) * STAGEB);
            compute_stage(stg, stg + ASTG, warp_m, warp_n, lane, acc);
            __syncthreads();
        }

        // epilogue: bias + gelu -> H fp16
        const float* bp = b1 + e * F_FF + col0;
#pragma unroll
        for (int mt = 0; mt < 4; mt++) {
#pragma unroll
            for (int h = 0; h < 2; h++) {
                int r = row0 + warp_m + mt * 16 + g + h * 8;
                __half* Hrow = g_Hh + ((size_t)e * CAP + r) * F_FF + col0;
#pragma unroll
                for (int nt = 0; nt < 4; nt++) {
                    int c = warp_n + nt * 8 + 2 * t4;
                    float v0 = acc[mt][nt][2 * h + 0] + bp[c];
                    float v1 = acc[mt][nt][2 * h + 1] + bp[c + 1];
                    v0 = 0.5f * v0 * (1.f + erff(v0 * 0.70710678118654752f));
                    v1 = 0.5f * v1 * (1.f + erff(v1 * 0.70710678118654752f));
                    *(__half2*)(Hrow + c) = __floats2half2_rn(v0, v1);
                }
            }
        }
        // publish completion
        __syncthreads();
        if (tid == 0) {
            __threadfence();
            atomicAdd(&g_ready[erb], 1);
        }
    } else {
        // ---------------- GEMM2 tile ----------------
        int b2id = bid - G1B;
        int cb = b2id & 7;                 // 8 col tiles
        int erb = b2id >> 3;
        int e = erb / NRB;
        int row0 = (erb % NRB) * BM;
        int cnt = g_cnt[e];
        if (row0 >= cnt) return;
        int col0 = cb * BN;

        // wait for all 16 gemm1 col-tiles of (e, rowblk)
        if (tid == 0) {
            while (atomicAdd(&g_ready[erb], 0) < 16) __nanosleep(200);
        }
        __syncthreads();
        __threadfence();

        const __half* aP[4];
        const __half* bP[4];
        uint32_t stA[4], stB[4];
        const __half* w2e = g_w2h + (size_t)e * D_MODEL * F_FF;
        const __half* He = g_Hh + (size_t)e * CAP * F_FF;
#pragma unroll
        for (int q = 0; q < 4; q++) {
            int r = rbt + 32 * q;
            aP[q] = He + (size_t)(row0 + r) * F_FF + c8 * 8;
            stA[q] = sb + (uint32_t)((r << 7) + ((c8 ^ (r & 7)) << 4));
            bP[q] = w2e + (size_t)(col0 + r) * F_FF + c8 * 8;
            stB[q] = sb + ASTG + stA[q] - sb;
        }

        float acc[4][4][4];
#pragma unroll
        for (int mt = 0; mt < 4; mt++)
#pragma unroll
            for (int nt = 0; nt < 4; nt++)
#pragma unroll
                for (int k = 0; k < 4; k++) acc[mt][nt][k] = 0.f;

        const int NCH = F_FF / 64;   // 32
#pragma unroll
        for (int c = 0; c < 2; c++) {
            uint32_t so = (uint32_t)(c * STAGEB);
#pragma unroll
            for (int q = 0; q < 4; q++) {
                cp16(stA[q] + so, aP[q]); aP[q] += 64;
                cp16(stB[q] + so, bP[q]); bP[q] += 64;
            }
            asm volatile("cp.async.commit_group;" ::: "memory");
        }
        for (int i = 0; i < NCH; i++) {
            if (i + 2 < NCH) {
                uint32_t so = (uint32_t)(((i + 2) % NSTAGE) * STAGEB);
#pragma unroll
                for (int q = 0; q < 4; q++) {
                    cp16(stA[q] + so, aP[q]); aP[q] += 64;
                    cp16(stB[q] + so, bP[q]); bP[q] += 64;
                }
                asm volatile("cp.async.commit_group;" ::: "memory");
                asm volatile("cp.async.wait_group 2;" ::: "memory");
            } else if (i + 1 < NCH) {
                asm volatile("cp.async.wait_group 1;" ::: "memory");
            } else {
                asm volatile("cp.async.wait_group 0;" ::: "memory");
            }
            __syncthreads();
            uint32_t stg = sb + (uint32_t)((i % NSTAGE) * STAGEB);
            compute_stage(stg, stg + ASTG, warp_m, warp_n, lane, acc);
            __syncthreads();
        }

        // epilogue: bias + gate + vector-red scatter
        const float* bp = b2 + e * D_MODEL + col0;
#pragma unroll
        for (int mt = 0; mt < 4; mt++) {
#pragma unroll
            for (int h = 0; h < 2; h++) {
                int r = row0 + warp_m + mt * 16 + g + h * 8;
                if (r < cnt) {
                    int   tok = g_slot_tok[e * CAP + r];
                    float w   = g_slot_w[e * CAP + r];
                    float* orow = out + (size_t)tok * D_MODEL + col0;
#pragma unroll
                    for (int nt = 0; nt < 4; nt++) {
                        int c = warp_n + nt * 8 + 2 * t4;
                        red2(orow + c,
                             (acc[mt][nt][2 * h + 0] + bp[c])     * w,
                             (acc[mt][nt][2 * h + 1] + bp[c + 1]) * w);
                    }
                }
            }
        }
    }
}

// ---------------------------------------------------------------------------
extern "C" void kernel_launch(void* const* d_in, const int* in_sizes, int n_in,
                              void* d_out, int out_size) {
    const float* x  = (const float*)d_in[0];
    const float* rw = (const float*)d_in[1];
    const float* rb = (const float*)d_in[2];
    const float* w1 = (const float*)d_in[3];
    const float* b1 = (const float*)d_in[4];
    const float* w2 = (const float*)d_in[5];
    const float* b2 = (const float*)d_in[6];
    float* out = (float*)d_out;

    cudaFuncSetAttribute(fused_gemm_kernel, cudaFuncAttributeMaxDynamicSharedMemorySize, DSMEM_BYTES);

    int n4 = out_size / 4;
    zero_kernel<<<(n4 + 255) / 256, 256>>>((float4*)out, n4);

    router_kernel<<<T_TOK / 8, 256>>>(x, rw, rb);
    rank_kernel<<<1, 256>>>();

    {   // transpose + convert weights to fp16
        __half *w1h, *w2h;
        cudaGetSymbolAddress((void**)&w1h, g_w1h);
        cudaGetSymbolAddress((void**)&w2h, g_w2h);
        dim3 b(32, 8);
        dim3 g1(F_FF / 32, D_MODEL / 32, NE);   // w1: R=D, C=F
        transpose_kernel<<<g1, b>>>(w1, w1h, D_MODEL, F_FF);
        dim3 g2(D_MODEL / 32, F_FF / 32, NE);   // w2: R=F, C=D
        transpose_kernel<<<g2, b>>>(w2, w2h, F_FF, D_MODEL);
    }

    fused_gemm_kernel<<<G1B + G2B, 256, DSMEM_BYTES>>>(b1, b2, out);
}